// round 1
// baseline (speedup 1.0000x reference)
#include <cuda_runtime.h>
#include <math.h>

#define B_   4
#define T_   2048
#define D_   2048
#define NH   16
#define NKV  4
#define HD   128
#define KVD  (NKV*HD)   // 512

// Scratch (allocation-free rule: __device__ globals)
__device__ float g_Q[(size_t)B_ * T_ * D_];    // [B,T,16,128]
__device__ float g_K[(size_t)B_ * T_ * KVD];   // [B,T,4,128]
__device__ float g_V[(size_t)B_ * T_ * KVD];
__device__ float g_O[(size_t)B_ * T_ * D_];

// ---------------------------------------------------------------------------
// NT SGEMM: C[m,n] = sum_k A[m*K+k] * B[n*K+k]. M,N % 128 == 0, K % 16 == 0.
// 128x128 tile, BK=16, 256 threads, 8x8 per thread.
// ---------------------------------------------------------------------------
__global__ __launch_bounds__(256) void sgemm_nt(const float* __restrict__ A,
                                                const float* __restrict__ B,
                                                float* __restrict__ C,
                                                int M, int N, int K)
{
    __shared__ float As[16][132];
    __shared__ float Bs[16][132];

    const int tid = threadIdx.x;
    const int tx  = tid & 15;        // 0..15 -> 8 cols each
    const int ty  = tid >> 4;        // 0..15 -> 8 rows each
    const int lr  = tid >> 2;        // 0..63 load row
    const int lk  = (tid & 3) << 2;  // 0,4,8,12 load k (float4)

    const float* Ab = A + (size_t)blockIdx.y * 128 * K;
    const float* Bb = B + (size_t)blockIdx.x * 128 * K;

    float acc[8][8];
#pragma unroll
    for (int i = 0; i < 8; i++)
#pragma unroll
        for (int j = 0; j < 8; j++) acc[i][j] = 0.f;

    for (int k0 = 0; k0 < K; k0 += 16) {
#pragma unroll
        for (int h = 0; h < 2; h++) {
            const int row = lr + h * 64;
            float4 a = *(const float4*)(Ab + (size_t)row * K + k0 + lk);
            As[lk + 0][row] = a.x; As[lk + 1][row] = a.y;
            As[lk + 2][row] = a.z; As[lk + 3][row] = a.w;
            float4 b = *(const float4*)(Bb + (size_t)row * K + k0 + lk);
            Bs[lk + 0][row] = b.x; Bs[lk + 1][row] = b.y;
            Bs[lk + 2][row] = b.z; Bs[lk + 3][row] = b.w;
        }
        __syncthreads();
#pragma unroll
        for (int k = 0; k < 16; k++) {
            float4 a0 = *(const float4*)&As[k][ty * 8];
            float4 a1 = *(const float4*)&As[k][ty * 8 + 4];
            float4 b0 = *(const float4*)&Bs[k][tx * 8];
            float4 b1 = *(const float4*)&Bs[k][tx * 8 + 4];
            const float av[8] = {a0.x,a0.y,a0.z,a0.w,a1.x,a1.y,a1.z,a1.w};
            const float bv[8] = {b0.x,b0.y,b0.z,b0.w,b1.x,b1.y,b1.z,b1.w};
#pragma unroll
            for (int i = 0; i < 8; i++)
#pragma unroll
                for (int j = 0; j < 8; j++) acc[i][j] += av[i] * bv[j];
        }
        __syncthreads();
    }

    float* Cb = C + (size_t)(blockIdx.y * 128 + ty * 8) * N + blockIdx.x * 128 + tx * 8;
#pragma unroll
    for (int i = 0; i < 8; i++) {
        *(float4*)(Cb + (size_t)i * N)     = make_float4(acc[i][0], acc[i][1], acc[i][2], acc[i][3]);
        *(float4*)(Cb + (size_t)i * N + 4) = make_float4(acc[i][4], acc[i][5], acc[i][6], acc[i][7]);
    }
}

// ---------------------------------------------------------------------------
// RoPE in place on g_Q (16 heads) and g_K (4 heads).
// inv_freq[i] = 10000^(-i/64), i = 0..63.  q'[i] = x1 c - x2 s ; q'[i+64] = x1 s + x2 c
// ---------------------------------------------------------------------------
__global__ void rope_kernel()
{
    const int t = blockIdx.x;
    const int b = blockIdx.y;
    const float LOG2_10000_OVER_64 = 0.20762050593045952f;  // log2(10000)/64
    for (int idx = threadIdx.x; idx < (NH + NKV) * 64; idx += blockDim.x) {
        const int head = idx >> 6;
        const int i    = idx & 63;
        const float invf = exp2f(-(float)i * LOG2_10000_OVER_64);
        const float ang  = (float)t * invf;
        float s, c;
        sincosf(ang, &s, &c);
        float* p;
        if (head < NH) p = g_Q + ((size_t)(b * T_ + t) * D_ + head * HD);
        else           p = g_K + ((size_t)(b * T_ + t) * KVD + (head - NH) * HD);
        const float x1 = p[i];
        const float x2 = p[i + 64];
        p[i]      = x1 * c - x2 * s;
        p[i + 64] = x1 * s + x2 * c;
    }
}

// ---------------------------------------------------------------------------
// Causal flash attention, fp32.  CTA = one (b, head, 64-row Q tile).
// 256 threads: thread = (r = tid>>2 in 0..63 query row, c = tid&3 col-quarter).
// Each thread owns O[r, c*32 .. c*32+31].
// smem: Qs/Ks/Vs 64x132 (padded), Ss 64x65.
// ---------------------------------------------------------------------------
#define ATT_SMEM_FLOATS (3 * 64 * 132 + 64 * 65)

__global__ __launch_bounds__(256) void attn_kernel()
{
    extern __shared__ float sm[];
    float* Qs = sm;
    float* Ks = sm + 64 * 132;
    float* Vs = sm + 2 * 64 * 132;
    float* Ss = sm + 3 * 64 * 132;

    const int qt  = blockIdx.x;   // 0..31
    const int h   = blockIdx.y;   // 0..15
    const int b   = blockIdx.z;   // 0..3
    const int kvh = h >> 2;
    const int tid = threadIdx.x;
    const int r   = tid >> 2;
    const int c   = tid & 3;

    // Load Q tile (64 x 128)
    for (int f = tid; f < 64 * 32; f += 256) {
        const int row = f >> 5, q4 = f & 31;
        *(float4*)&Qs[row * 132 + q4 * 4] =
            *(const float4*)(g_Q + ((size_t)(b * T_ + qt * 64 + row) * D_ + h * HD + q4 * 4));
    }

    float o[32];
#pragma unroll
    for (int u = 0; u < 32; u++) o[u] = 0.f;
    float m = -INFINITY, l = 0.f;
    const float scale = 0.08838834764831845f;  // 1/sqrt(128)
    const int qrow = qt * 64 + r;

    for (int j = 0; j <= qt; j++) {
        __syncthreads();  // previous PV done before overwriting K/V
        for (int f = tid; f < 64 * 32; f += 256) {
            const int row = f >> 5, q4 = f & 31;
            const size_t gk = (size_t)(b * T_ + j * 64 + row) * KVD + kvh * HD + q4 * 4;
            *(float4*)&Ks[row * 132 + q4 * 4] = *(const float4*)(g_K + gk);
            *(float4*)&Vs[row * 132 + q4 * 4] = *(const float4*)(g_V + gk);
        }
        __syncthreads();

        // S = Q K^T for this thread's 16 columns (jg = c*16 + jj)
        float sl[16];
#pragma unroll
        for (int jj = 0; jj < 16; jj++) sl[jj] = 0.f;
        for (int kc = 0; kc < 32; kc += 8) {
            float4 q[8];
#pragma unroll
            for (int u = 0; u < 8; u++) q[u] = *(const float4*)&Qs[r * 132 + (kc + u) * 4];
#pragma unroll
            for (int jj = 0; jj < 16; jj++) {
                const int jg = c * 16 + jj;
                float acc = 0.f;
#pragma unroll
                for (int u = 0; u < 8; u++) {
                    const float4 kv = *(const float4*)&Ks[jg * 132 + (kc + u) * 4];
                    acc += q[u].x * kv.x + q[u].y * kv.y + q[u].z * kv.z + q[u].w * kv.w;
                }
                sl[jj] += acc;
            }
        }

        float mx = -INFINITY;
#pragma unroll
        for (int jj = 0; jj < 16; jj++) {
            const int kcol = j * 64 + c * 16 + jj;
            float v = sl[jj] * scale;
            if (kcol > qrow) v = -INFINITY;
            sl[jj] = v;
            mx = fmaxf(mx, v);
        }
        mx = fmaxf(mx, __shfl_xor_sync(0xffffffffu, mx, 1, 4));
        mx = fmaxf(mx, __shfl_xor_sync(0xffffffffu, mx, 2, 4));

        const float mnew  = fmaxf(m, mx);
        const float alpha = __expf(m - mnew);
        float psum = 0.f;
#pragma unroll
        for (int jj = 0; jj < 16; jj++) {
            const float p = __expf(sl[jj] - mnew);
            Ss[r * 65 + c * 16 + jj] = p;
            psum += p;
        }
        psum += __shfl_xor_sync(0xffffffffu, psum, 1, 4);
        psum += __shfl_xor_sync(0xffffffffu, psum, 2, 4);
        l = l * alpha + psum;
        m = mnew;
#pragma unroll
        for (int u = 0; u < 32; u++) o[u] *= alpha;

        __syncthreads();  // Ss visible to all 4 col-quarters of each row

        // O += P @ V   (this thread: full P row x V[:, c*32 .. c*32+31])
        for (int jj = 0; jj < 64; jj++) {
            const float p = Ss[r * 65 + jj];
            const float4* vr = (const float4*)&Vs[jj * 132 + c * 32];
#pragma unroll
            for (int u = 0; u < 8; u++) {
                const float4 v = vr[u];
                o[u * 4 + 0] += p * v.x;
                o[u * 4 + 1] += p * v.y;
                o[u * 4 + 2] += p * v.z;
                o[u * 4 + 3] += p * v.w;
            }
        }
    }

    const float inv = 1.f / l;
    float* op = g_O + ((size_t)(b * T_ + qrow) * D_ + h * HD + c * 32);
#pragma unroll
    for (int u = 0; u < 8; u++) {
        *(float4*)(op + u * 4) = make_float4(o[u * 4 + 0] * inv, o[u * 4 + 1] * inv,
                                             o[u * 4 + 2] * inv, o[u * 4 + 3] * inv);
    }
}

// ---------------------------------------------------------------------------
extern "C" void kernel_launch(void* const* d_in, const int* in_sizes, int n_in,
                              void* d_out, int out_size)
{
    const float* x  = (const float*)d_in[0];
    const float* Wq = (const float*)d_in[1];
    const float* Wk = (const float*)d_in[2];
    const float* Wv = (const float*)d_in[3];
    const float* Wo = (const float*)d_in[4];
    float* out = (float*)d_out;

    float *Qb, *Kb, *Vb, *Ob;
    cudaGetSymbolAddress((void**)&Qb, g_Q);
    cudaGetSymbolAddress((void**)&Kb, g_K);
    cudaGetSymbolAddress((void**)&Vb, g_V);
    cudaGetSymbolAddress((void**)&Ob, g_O);

    const int M = B_ * T_;  // 8192

    // Projections: row-major A [M,K] x row-major W [N,K] (NT)
    sgemm_nt<<<dim3(D_ / 128, M / 128), 256>>>(x, Wq, Qb, M, D_, D_);
    sgemm_nt<<<dim3(KVD / 128, M / 128), 256>>>(x, Wk, Kb, M, KVD, D_);
    sgemm_nt<<<dim3(KVD / 128, M / 128), 256>>>(x, Wv, Vb, M, KVD, D_);

    // RoPE on Q and K
    rope_kernel<<<dim3(T_, B_), 256>>>();

    // Attention
    static const size_t att_smem = ATT_SMEM_FLOATS * sizeof(float);
    cudaFuncSetAttribute(attn_kernel, cudaFuncAttributeMaxDynamicSharedMemorySize,
                         (int)att_smem);
    attn_kernel<<<dim3(T_ / 64, NH, B_), 256, att_smem>>>();

    // Output projection
    sgemm_nt<<<dim3(D_ / 128, M / 128), 256>>>(Ob, Wo, out, M, D_, D_);
}

// round 3
// speedup vs baseline: 1.1030x; 1.1030x over previous
#include <cuda_runtime.h>
#include <cuda_bf16.h>
#include <math.h>
#include <stdint.h>

#define B_   4
#define T_   2048
#define D_   2048
#define NH   16
#define NKV  4
#define HD   128
#define KVD  (NKV*HD)   // 512
#define KP   (3*D_)     // 6144 split-expanded K

// ---------------- scratch (__device__ globals; allocation-free rule) -------
__device__ float g_Q[(size_t)B_ * T_ * D_];
__device__ float g_K[(size_t)B_ * T_ * KVD];
__device__ float g_V[(size_t)B_ * T_ * KVD];
__device__ float g_O[(size_t)B_ * T_ * D_];

__device__ __nv_bfloat16 g_AE [(size_t)(B_*T_) * KP];   // x-expand, reused for O-expand
__device__ __nv_bfloat16 g_WQE[(size_t)D_  * KP];
__device__ __nv_bfloat16 g_WKE[(size_t)KVD * KP];
__device__ __nv_bfloat16 g_WVE[(size_t)KVD * KP];
__device__ __nv_bfloat16 g_WOE[(size_t)D_  * KP];

// ---------------- helpers --------------------------------------------------
__device__ __forceinline__ uint32_t smem_u32(const void* p) {
    uint32_t a;
    asm("{ .reg .u64 t; cvta.to.shared.u64 t, %1; cvt.u32.u64 %0, t; }" : "=r"(a) : "l"(p));
    return a;
}
#define CP_ASYNC16(dst, src) \
    asm volatile("cp.async.cg.shared.global [%0], [%1], 16;" :: "r"(dst), "l"(src) : "memory")
#define CP_COMMIT() asm volatile("cp.async.commit_group;" ::: "memory")
#define CP_WAIT(N)  asm volatile("cp.async.wait_group %0;" :: "n"(N) : "memory")

#define LDMATRIX_X4(r0, r1, r2, r3, addr) \
    asm volatile("ldmatrix.sync.aligned.m8n8.x4.shared.b16 {%0,%1,%2,%3}, [%4];" \
        : "=r"(r0), "=r"(r1), "=r"(r2), "=r"(r3) : "r"(addr))

#define MMA_BF16(d, a, b0, b1) \
    asm volatile("mma.sync.aligned.m16n8k16.row.col.f32.bf16.bf16.f32 " \
        "{%0,%1,%2,%3}, {%4,%5,%6,%7}, {%8,%9}, {%0,%1,%2,%3};" \
        : "+f"((d)[0]), "+f"((d)[1]), "+f"((d)[2]), "+f"((d)[3]) \
        : "r"((a)[0]), "r"((a)[1]), "r"((a)[2]), "r"((a)[3]), "r"(b0), "r"(b1))

// ---------------------------------------------------------------------------
// split conversion: fp32 [M,K] -> bf16 [M,3K]
// amode (bmode=0): [hi | hi | lo]    bmode=1: [hi | lo | hi]
// ---------------------------------------------------------------------------
__global__ void split_kernel(const float* __restrict__ in, __nv_bfloat16* __restrict__ out,
                             int K, int bmode, size_t total)
{
    for (size_t e = (size_t)blockIdx.x * blockDim.x + threadIdx.x; e < total;
         e += (size_t)gridDim.x * blockDim.x) {
        size_t m = e / (size_t)K;
        int k = (int)(e - m * (size_t)K);
        float v = in[e];
        __nv_bfloat16 hi = __float2bfloat16(v);
        __nv_bfloat16 lo = __float2bfloat16(v - __bfloat162float(hi));
        __nv_bfloat16* row = out + m * (size_t)(3 * K);
        row[k]         = hi;
        row[K + k]     = bmode ? lo : hi;
        row[2 * K + k] = bmode ? hi : lo;
    }
}

// ---------------------------------------------------------------------------
// HMMA bf16 NT GEMM: C[m,n] = sum_k A[m,k]*B[n,k]; A:[M,Kp] B:[N,Kp] bf16,
// C fp32 row-major [M,N]. Tile 128x128, BK=32, 256 thr (8 warps, 4m x 2n),
// warp tile 32x64 (2 m16 x 8 n8), 3-stage cp.async, padded smem stride 80B.
// ---------------------------------------------------------------------------
#define GBK        32
#define G_STRIDE_B 80                     // bytes per padded row (40 bf16)
#define G_TILE_B   (128 * G_STRIDE_B)     // 10240 bytes per operand tile
#define G_NSTAGE   3
#define GEMM_SMEM  (G_NSTAGE * 2 * G_TILE_B)   // 61440

__global__ __launch_bounds__(256, 2)
void gemm_bf16_nt(const __nv_bfloat16* __restrict__ A, const __nv_bfloat16* __restrict__ B,
                  float* __restrict__ C, int N, int Kp)
{
    extern __shared__ char smraw[];
    const uint32_t smem = smem_u32(smraw);

    const int tid    = threadIdx.x;
    const int lane   = tid & 31;
    const int wid    = tid >> 5;
    const int warp_m = wid & 3;    // 0..3 -> 32 rows each
    const int warp_n = wid >> 2;   // 0..1 -> 64 cols each

    const __nv_bfloat16* Ag = A + (size_t)blockIdx.y * 128 * Kp;
    const __nv_bfloat16* Bg = B + (size_t)blockIdx.x * 128 * Kp;
    const int nch = Kp / GBK;

    auto load_chunk = [&](int chunk, int buf) {
        const uint32_t sa = smem + buf * 2 * G_TILE_B;
        const uint32_t sb = sa + G_TILE_B;
        const int k0 = chunk * GBK;
#pragma unroll
        for (int j = 0; j < 2; j++) {
            const int p   = tid + (j << 8);       // 0..511
            const int row = p >> 2;
            const int c16 = p & 3;
            const uint32_t off = (uint32_t)(row * G_STRIDE_B + c16 * 16);
            const size_t gsrc = (size_t)row * Kp + k0 + c16 * 8;
            CP_ASYNC16(sa + off, Ag + gsrc);
            CP_ASYNC16(sb + off, Bg + gsrc);
        }
        CP_COMMIT();
    };

    float acc[2][8][4];
#pragma unroll
    for (int t = 0; t < 2; t++)
#pragma unroll
        for (int n = 0; n < 8; n++)
#pragma unroll
            for (int x = 0; x < 4; x++) acc[t][n][x] = 0.f;

    load_chunk(0, 0);
    load_chunk(1, 1);

    // per-lane ldmatrix base offsets (within a tile)
    const uint32_t lm_row = (uint32_t)((lane & 15) * G_STRIDE_B + (lane >> 4) * 16);
    const uint32_t a_off  = (uint32_t)(warp_m * 32 * G_STRIDE_B) + lm_row;
    const uint32_t b_off  = (uint32_t)(warp_n * 64 * G_STRIDE_B) + lm_row;

    for (int i = 0; i < nch; i++) {
        if (i == nch - 1) { CP_WAIT(0); } else { CP_WAIT(1); }
        __syncthreads();
        if (i + 2 < nch) load_chunk(i + 2, (i + 2) % G_NSTAGE);

        const uint32_t sa = smem + (i % G_NSTAGE) * 2 * G_TILE_B;
        const uint32_t sb = sa + G_TILE_B;
#pragma unroll
        for (int s = 0; s < 2; s++) {           // two k16 steps in BK=32
            const uint32_t ks = (uint32_t)(s * 32);   // 16 bf16 = 32 bytes
            uint32_t af[2][4];
#pragma unroll
            for (int t = 0; t < 2; t++)
                LDMATRIX_X4(af[t][0], af[t][1], af[t][2], af[t][3],
                            sa + a_off + (uint32_t)(t * 16 * G_STRIDE_B) + ks);
            uint32_t bf[4][4];
#pragma unroll
            for (int p = 0; p < 4; p++)
                LDMATRIX_X4(bf[p][0], bf[p][1], bf[p][2], bf[p][3],
                            sb + b_off + (uint32_t)(p * 16 * G_STRIDE_B) + ks);
#pragma unroll
            for (int t = 0; t < 2; t++)
#pragma unroll
                for (int p = 0; p < 4; p++) {
                    MMA_BF16(acc[t][2 * p],     af[t], bf[p][0], bf[p][2]);
                    MMA_BF16(acc[t][2 * p + 1], af[t], bf[p][1], bf[p][3]);
                }
        }
    }

    // epilogue: direct global stores
#pragma unroll
    for (int t = 0; t < 2; t++) {
        const int row0 = blockIdx.y * 128 + warp_m * 32 + t * 16 + (lane >> 2);
#pragma unroll
        for (int n = 0; n < 8; n++) {
            const int col = blockIdx.x * 128 + warp_n * 64 + n * 8 + (lane & 3) * 2;
            *(float2*)(C + (size_t)row0 * N + col) =
                make_float2(acc[t][n][0], acc[t][n][1]);
            *(float2*)(C + (size_t)(row0 + 8) * N + col) =
                make_float2(acc[t][n][2], acc[t][n][3]);
        }
    }
}

// ---------------------------------------------------------------------------
// RoPE in place on g_Q (16 heads) and g_K (4 heads).
// ---------------------------------------------------------------------------
__global__ void rope_kernel()
{
    const int t = blockIdx.x;
    const int b = blockIdx.y;
    const float LOG2_10000_OVER_64 = 0.20762050593045952f;
    for (int idx = threadIdx.x; idx < (NH + NKV) * 64; idx += blockDim.x) {
        const int head = idx >> 6;
        const int i    = idx & 63;
        const float invf = exp2f(-(float)i * LOG2_10000_OVER_64);
        const float ang  = (float)t * invf;
        float s, c;
        sincosf(ang, &s, &c);
        float* p;
        if (head < NH) p = g_Q + ((size_t)(b * T_ + t) * D_ + head * HD);
        else           p = g_K + ((size_t)(b * T_ + t) * KVD + (head - NH) * HD);
        const float x1 = p[i];
        const float x2 = p[i + 64];
        p[i]      = x1 * c - x2 * s;
        p[i + 64] = x1 * s + x2 * c;
    }
}

// ---------------------------------------------------------------------------
// Causal flash attention, fp32 (unchanged passing version).
// ---------------------------------------------------------------------------
#define ATT_SMEM_FLOATS (3 * 64 * 132 + 64 * 65)

__global__ __launch_bounds__(256) void attn_kernel()
{
    extern __shared__ float sm[];
    float* Qs = sm;
    float* Ks = sm + 64 * 132;
    float* Vs = sm + 2 * 64 * 132;
    float* Ss = sm + 3 * 64 * 132;

    const int qt  = blockIdx.x;
    const int h   = blockIdx.y;
    const int b   = blockIdx.z;
    const int kvh = h >> 2;
    const int tid = threadIdx.x;
    const int r   = tid >> 2;
    const int c   = tid & 3;

    for (int f = tid; f < 64 * 32; f += 256) {
        const int row = f >> 5, q4 = f & 31;
        *(float4*)&Qs[row * 132 + q4 * 4] =
            *(const float4*)(g_Q + ((size_t)(b * T_ + qt * 64 + row) * D_ + h * HD + q4 * 4));
    }

    float o[32];
#pragma unroll
    for (int u = 0; u < 32; u++) o[u] = 0.f;
    float m = -INFINITY, l = 0.f;
    const float scale = 0.08838834764831845f;
    const int qrow = qt * 64 + r;

    for (int j = 0; j <= qt; j++) {
        __syncthreads();
        for (int f = tid; f < 64 * 32; f += 256) {
            const int row = f >> 5, q4 = f & 31;
            const size_t gk = (size_t)(b * T_ + j * 64 + row) * KVD + kvh * HD + q4 * 4;
            *(float4*)&Ks[row * 132 + q4 * 4] = *(const float4*)(g_K + gk);
            *(float4*)&Vs[row * 132 + q4 * 4] = *(const float4*)(g_V + gk);
        }
        __syncthreads();

        float sl[16];
#pragma unroll
        for (int jj = 0; jj < 16; jj++) sl[jj] = 0.f;
        for (int kc = 0; kc < 32; kc += 8) {
            float4 q[8];
#pragma unroll
            for (int u = 0; u < 8; u++) q[u] = *(const float4*)&Qs[r * 132 + (kc + u) * 4];
#pragma unroll
            for (int jj = 0; jj < 16; jj++) {
                const int jg = c * 16 + jj;
                float acc = 0.f;
#pragma unroll
                for (int u = 0; u < 8; u++) {
                    const float4 kv = *(const float4*)&Ks[jg * 132 + (kc + u) * 4];
                    acc += q[u].x * kv.x + q[u].y * kv.y + q[u].z * kv.z + q[u].w * kv.w;
                }
                sl[jj] += acc;
            }
        }

        float mx = -INFINITY;
#pragma unroll
        for (int jj = 0; jj < 16; jj++) {
            const int kcol = j * 64 + c * 16 + jj;
            float v = sl[jj] * scale;
            if (kcol > qrow) v = -INFINITY;
            sl[jj] = v;
            mx = fmaxf(mx, v);
        }
        mx = fmaxf(mx, __shfl_xor_sync(0xffffffffu, mx, 1, 4));
        mx = fmaxf(mx, __shfl_xor_sync(0xffffffffu, mx, 2, 4));

        const float mnew  = fmaxf(m, mx);
        const float alpha = __expf(m - mnew);
        float psum = 0.f;
#pragma unroll
        for (int jj = 0; jj < 16; jj++) {
            const float p = __expf(sl[jj] - mnew);
            Ss[r * 65 + c * 16 + jj] = p;
            psum += p;
        }
        psum += __shfl_xor_sync(0xffffffffu, psum, 1, 4);
        psum += __shfl_xor_sync(0xffffffffu, psum, 2, 4);
        l = l * alpha + psum;
        m = mnew;
#pragma unroll
        for (int u = 0; u < 32; u++) o[u] *= alpha;

        __syncthreads();

        for (int jj = 0; jj < 64; jj++) {
            const float p = Ss[r * 65 + jj];
            const float4* vr = (const float4*)&Vs[jj * 132 + c * 32];
#pragma unroll
            for (int u = 0; u < 8; u++) {
                const float4 v = vr[u];
                o[u * 4 + 0] += p * v.x;
                o[u * 4 + 1] += p * v.y;
                o[u * 4 + 2] += p * v.z;
                o[u * 4 + 3] += p * v.w;
            }
        }
    }

    const float inv = 1.f / l;
    float* op = g_O + ((size_t)(b * T_ + qrow) * D_ + h * HD + c * 32);
#pragma unroll
    for (int u = 0; u < 8; u++) {
        *(float4*)(op + u * 4) = make_float4(o[u * 4 + 0] * inv, o[u * 4 + 1] * inv,
                                             o[u * 4 + 2] * inv, o[u * 4 + 3] * inv);
    }
}

// ---------------------------------------------------------------------------
extern "C" void kernel_launch(void* const* d_in, const int* in_sizes, int n_in,
                              void* d_out, int out_size)
{
    const float* x  = (const float*)d_in[0];
    const float* Wq = (const float*)d_in[1];
    const float* Wk = (const float*)d_in[2];
    const float* Wv = (const float*)d_in[3];
    const float* Wo = (const float*)d_in[4];
    float* out = (float*)d_out;

    float *Qb, *Kb, *Vb, *Ob;
    __nv_bfloat16 *AE, *WQE, *WKE, *WVE, *WOE;
    cudaGetSymbolAddress((void**)&Qb, g_Q);
    cudaGetSymbolAddress((void**)&Kb, g_K);
    cudaGetSymbolAddress((void**)&Vb, g_V);
    cudaGetSymbolAddress((void**)&Ob, g_O);
    cudaGetSymbolAddress((void**)&AE, g_AE);
    cudaGetSymbolAddress((void**)&WQE, g_WQE);
    cudaGetSymbolAddress((void**)&WKE, g_WKE);
    cudaGetSymbolAddress((void**)&WVE, g_WVE);
    cudaGetSymbolAddress((void**)&WOE, g_WOE);

    const int M = B_ * T_;  // 8192

    cudaFuncSetAttribute(gemm_bf16_nt, cudaFuncAttributeMaxDynamicSharedMemorySize,
                         GEMM_SMEM);
    static const size_t att_smem = ATT_SMEM_FLOATS * sizeof(float);
    cudaFuncSetAttribute(attn_kernel, cudaFuncAttributeMaxDynamicSharedMemorySize,
                         (int)att_smem);

    // split conversions
    split_kernel<<<4096, 256>>>(x,  AE,  D_, 0, (size_t)M * D_);
    split_kernel<<<2048, 256>>>(Wq, WQE, D_, 1, (size_t)D_ * D_);
    split_kernel<<<1024, 256>>>(Wk, WKE, D_, 1, (size_t)KVD * D_);
    split_kernel<<<1024, 256>>>(Wv, WVE, D_, 1, (size_t)KVD * D_);
    split_kernel<<<2048, 256>>>(Wo, WOE, D_, 1, (size_t)D_ * D_);

    // projections on tensor cores (HMMA)
    gemm_bf16_nt<<<dim3(D_ / 128, M / 128), 256, GEMM_SMEM>>>(AE, WQE, Qb, D_, KP);
    gemm_bf16_nt<<<dim3(KVD / 128, M / 128), 256, GEMM_SMEM>>>(AE, WKE, Kb, KVD, KP);
    gemm_bf16_nt<<<dim3(KVD / 128, M / 128), 256, GEMM_SMEM>>>(AE, WVE, Vb, KVD, KP);

    rope_kernel<<<dim3(T_, B_), 256>>>();

    attn_kernel<<<dim3(T_ / 64, NH, B_), 256, att_smem>>>();

    // output projection: expand O into AE (x no longer needed), then GEMM
    split_kernel<<<4096, 256>>>(Ob, AE, D_, 0, (size_t)M * D_);
    gemm_bf16_nt<<<dim3(D_ / 128, M / 128), 256, GEMM_SMEM>>>(AE, WOE, out, D_, KP);
}

// round 4
// speedup vs baseline: 7.0811x; 6.4199x over previous
#include <cuda_runtime.h>
#include <cuda_bf16.h>
#include <math.h>
#include <stdint.h>

#define B_   4
#define T_   2048
#define D_   2048
#define NH   16
#define NKV  4
#define HD   128
#define KVD  (NKV*HD)   // 512
#define KP   (3*D_)     // 6144 split-expanded K for projections

// scale/sqrt(hd) * log2(e), folded into Q split
#define SCALE_LOG2E 0.1275174277208884f

// ---------------- scratch (__device__ globals; allocation-free rule) -------
__device__ float g_Q[(size_t)B_ * T_ * D_];
__device__ float g_K[(size_t)B_ * T_ * KVD];
__device__ float g_V[(size_t)B_ * T_ * KVD];
__device__ float g_O[(size_t)B_ * T_ * D_];

__device__ __nv_bfloat16 g_AE [(size_t)(B_*T_) * KP];
__device__ __nv_bfloat16 g_WQE[(size_t)D_  * KP];
__device__ __nv_bfloat16 g_WKE[(size_t)KVD * KP];
__device__ __nv_bfloat16 g_WVE[(size_t)KVD * KP];
__device__ __nv_bfloat16 g_WOE[(size_t)D_  * KP];

// attention split operands
__device__ __nv_bfloat16 g_Qe [(size_t)B_ * NH  * T_ * 384];  // [b,h,t,384] = Qh|Qh|Ql (roped, scaled)
__device__ __nv_bfloat16 g_Ke [(size_t)B_ * NKV * T_ * 384];  // [b,kvh,t,384] = Kh|Kl|Kh (roped)
__device__ __nv_bfloat16 g_Vth[(size_t)B_ * NKV * HD * T_];   // [b,kvh,d,t] hi
__device__ __nv_bfloat16 g_Vtl[(size_t)B_ * NKV * HD * T_];   // lo

// ---------------- helpers --------------------------------------------------
__device__ __forceinline__ uint32_t smem_u32(const void* p) {
    uint32_t a;
    asm("{ .reg .u64 t; cvta.to.shared.u64 t, %1; cvt.u32.u64 %0, t; }" : "=r"(a) : "l"(p));
    return a;
}
#define CP_ASYNC16(dst, src) \
    asm volatile("cp.async.cg.shared.global [%0], [%1], 16;" :: "r"(dst), "l"(src) : "memory")
#define CP_COMMIT() asm volatile("cp.async.commit_group;" ::: "memory")
#define CP_WAIT(N)  asm volatile("cp.async.wait_group %0;" :: "n"(N) : "memory")

#define LDMATRIX_X4(r0, r1, r2, r3, addr) \
    asm volatile("ldmatrix.sync.aligned.m8n8.x4.shared.b16 {%0,%1,%2,%3}, [%4];" \
        : "=r"(r0), "=r"(r1), "=r"(r2), "=r"(r3) : "r"(addr))

#define MMA_BF16(d, a, b0, b1) \
    asm volatile("mma.sync.aligned.m16n8k16.row.col.f32.bf16.bf16.f32 " \
        "{%0,%1,%2,%3}, {%4,%5,%6,%7}, {%8,%9}, {%0,%1,%2,%3};" \
        : "+f"((d)[0]), "+f"((d)[1]), "+f"((d)[2]), "+f"((d)[3]) \
        : "r"((a)[0]), "r"((a)[1]), "r"((a)[2]), "r"((a)[3]), "r"(b0), "r"(b1))

// ---------------------------------------------------------------------------
// split conversion: fp32 [M,K] -> bf16 [M,3K]
// ---------------------------------------------------------------------------
__global__ void split_kernel(const float* __restrict__ in, __nv_bfloat16* __restrict__ out,
                             int K, int bmode, size_t total)
{
    for (size_t e = (size_t)blockIdx.x * blockDim.x + threadIdx.x; e < total;
         e += (size_t)gridDim.x * blockDim.x) {
        size_t m = e / (size_t)K;
        int k = (int)(e - m * (size_t)K);
        float v = in[e];
        __nv_bfloat16 hi = __float2bfloat16(v);
        __nv_bfloat16 lo = __float2bfloat16(v - __bfloat162float(hi));
        __nv_bfloat16* row = out + m * (size_t)(3 * K);
        row[k]         = hi;
        row[K + k]     = bmode ? lo : hi;
        row[2 * K + k] = bmode ? hi : lo;
    }
}

// ---------------------------------------------------------------------------
// HMMA bf16 NT GEMM (unchanged from R3, passing)
// ---------------------------------------------------------------------------
#define GBK        32
#define G_STRIDE_B 80
#define G_TILE_B   (128 * G_STRIDE_B)
#define G_NSTAGE   3
#define GEMM_SMEM  (G_NSTAGE * 2 * G_TILE_B)

__global__ __launch_bounds__(256, 2)
void gemm_bf16_nt(const __nv_bfloat16* __restrict__ A, const __nv_bfloat16* __restrict__ B,
                  float* __restrict__ C, int N, int Kp)
{
    extern __shared__ char smraw[];
    const uint32_t smem = smem_u32(smraw);

    const int tid    = threadIdx.x;
    const int lane   = tid & 31;
    const int wid    = tid >> 5;
    const int warp_m = wid & 3;
    const int warp_n = wid >> 2;

    const __nv_bfloat16* Ag = A + (size_t)blockIdx.y * 128 * Kp;
    const __nv_bfloat16* Bg = B + (size_t)blockIdx.x * 128 * Kp;
    const int nch = Kp / GBK;

    auto load_chunk = [&](int chunk, int buf) {
        const uint32_t sa = smem + buf * 2 * G_TILE_B;
        const uint32_t sb = sa + G_TILE_B;
        const int k0 = chunk * GBK;
#pragma unroll
        for (int j = 0; j < 2; j++) {
            const int p   = tid + (j << 8);
            const int row = p >> 2;
            const int c16 = p & 3;
            const uint32_t off = (uint32_t)(row * G_STRIDE_B + c16 * 16);
            const size_t gsrc = (size_t)row * Kp + k0 + c16 * 8;
            CP_ASYNC16(sa + off, Ag + gsrc);
            CP_ASYNC16(sb + off, Bg + gsrc);
        }
        CP_COMMIT();
    };

    float acc[2][8][4];
#pragma unroll
    for (int t = 0; t < 2; t++)
#pragma unroll
        for (int n = 0; n < 8; n++)
#pragma unroll
            for (int x = 0; x < 4; x++) acc[t][n][x] = 0.f;

    load_chunk(0, 0);
    load_chunk(1, 1);

    const uint32_t lm_row = (uint32_t)((lane & 15) * G_STRIDE_B + (lane >> 4) * 16);
    const uint32_t a_off  = (uint32_t)(warp_m * 32 * G_STRIDE_B) + lm_row;
    const uint32_t b_off  = (uint32_t)(warp_n * 64 * G_STRIDE_B) + lm_row;

    for (int i = 0; i < nch; i++) {
        if (i == nch - 1) { CP_WAIT(0); } else { CP_WAIT(1); }
        __syncthreads();
        if (i + 2 < nch) load_chunk(i + 2, (i + 2) % G_NSTAGE);

        const uint32_t sa = smem + (i % G_NSTAGE) * 2 * G_TILE_B;
        const uint32_t sb = sa + G_TILE_B;
#pragma unroll
        for (int s = 0; s < 2; s++) {
            const uint32_t ks = (uint32_t)(s * 32);
            uint32_t af[2][4];
#pragma unroll
            for (int t = 0; t < 2; t++)
                LDMATRIX_X4(af[t][0], af[t][1], af[t][2], af[t][3],
                            sa + a_off + (uint32_t)(t * 16 * G_STRIDE_B) + ks);
            uint32_t bfr[4][4];
#pragma unroll
            for (int p = 0; p < 4; p++)
                LDMATRIX_X4(bfr[p][0], bfr[p][1], bfr[p][2], bfr[p][3],
                            sb + b_off + (uint32_t)(p * 16 * G_STRIDE_B) + ks);
#pragma unroll
            for (int t = 0; t < 2; t++)
#pragma unroll
                for (int p = 0; p < 4; p++) {
                    MMA_BF16(acc[t][2 * p],     af[t], bfr[p][0], bfr[p][2]);
                    MMA_BF16(acc[t][2 * p + 1], af[t], bfr[p][1], bfr[p][3]);
                }
        }
    }

#pragma unroll
    for (int t = 0; t < 2; t++) {
        const int row0 = blockIdx.y * 128 + warp_m * 32 + t * 16 + (lane >> 2);
#pragma unroll
        for (int n = 0; n < 8; n++) {
            const int col = blockIdx.x * 128 + warp_n * 64 + n * 8 + (lane & 3) * 2;
            *(float2*)(C + (size_t)row0 * N + col) =
                make_float2(acc[t][n][0], acc[t][n][1]);
            *(float2*)(C + (size_t)(row0 + 8) * N + col) =
                make_float2(acc[t][n][2], acc[t][n][3]);
        }
    }
}

// ---------------------------------------------------------------------------
// RoPE + hi/lo split for attention operands.
// Q': [b,h,t,384] = [Qh|Qh|Ql], scaled by SCALE_LOG2E.  K': [Kh|Kl|Kh].
// ---------------------------------------------------------------------------
__global__ void rope_split_kernel()
{
    const int t = blockIdx.x;
    const int b = blockIdx.y;
    const float LOG2_10000_OVER_64 = 0.20762050593045952f;

    // Q: 16 heads x 64 rotary pairs
    for (int idx = threadIdx.x; idx < NH * 64; idx += blockDim.x) {
        const int head = idx >> 6;
        const int i    = idx & 63;
        const float invf = exp2f(-(float)i * LOG2_10000_OVER_64);
        float s, c;
        sincosf((float)t * invf, &s, &c);
        const float* p = g_Q + ((size_t)(b * T_ + t) * D_ + head * HD);
        float q1 = p[i], q2 = p[i + 64];
        float r1 = (q1 * c - q2 * s) * SCALE_LOG2E;
        float r2 = (q1 * s + q2 * c) * SCALE_LOG2E;
        __nv_bfloat16 h1 = __float2bfloat16(r1);
        __nv_bfloat16 l1 = __float2bfloat16(r1 - __bfloat162float(h1));
        __nv_bfloat16 h2 = __float2bfloat16(r2);
        __nv_bfloat16 l2 = __float2bfloat16(r2 - __bfloat162float(h2));
        __nv_bfloat16* row = g_Qe + ((size_t)(b * NH + head) * T_ + t) * 384;
        row[i]        = h1;  row[i + 64]  = h2;
        row[128 + i]  = h1;  row[192 + i] = h2;
        row[256 + i]  = l1;  row[320 + i] = l2;
    }
    // K: 4 heads x 64 rotary pairs
    for (int idx = threadIdx.x; idx < NKV * 64; idx += blockDim.x) {
        const int kvh = idx >> 6;
        const int i   = idx & 63;
        const float invf = exp2f(-(float)i * LOG2_10000_OVER_64);
        float s, c;
        sincosf((float)t * invf, &s, &c);
        const float* p = g_K + ((size_t)(b * T_ + t) * KVD + kvh * HD);
        float q1 = p[i], q2 = p[i + 64];
        float r1 = q1 * c - q2 * s;
        float r2 = q1 * s + q2 * c;
        __nv_bfloat16 h1 = __float2bfloat16(r1);
        __nv_bfloat16 l1 = __float2bfloat16(r1 - __bfloat162float(h1));
        __nv_bfloat16 h2 = __float2bfloat16(r2);
        __nv_bfloat16 l2 = __float2bfloat16(r2 - __bfloat162float(h2));
        __nv_bfloat16* row = g_Ke + ((size_t)(b * NKV + kvh) * T_ + t) * 384;
        row[i]        = h1;  row[i + 64]  = h2;
        row[128 + i]  = l1;  row[192 + i] = l2;
        row[256 + i]  = h1;  row[320 + i] = h2;
    }
}

// V transpose + split:  g_V [b,t,kvh,d] fp32 -> g_Vth/g_Vtl [b,kvh,d,t] bf16
__global__ void v_split_kernel()
{
    const int t   = blockIdx.x * blockDim.x + threadIdx.x;
    const int d   = blockIdx.y;
    const int bz  = blockIdx.z;
    const int b   = bz >> 2, kvh = bz & 3;
    const float v = g_V[(size_t)(b * T_ + t) * KVD + kvh * HD + d];
    __nv_bfloat16 hi = __float2bfloat16(v);
    __nv_bfloat16 lo = __float2bfloat16(v - __bfloat162float(hi));
    const size_t o = ((size_t)bz * HD + d) * T_ + t;
    g_Vth[o] = hi;
    g_Vtl[o] = lo;
}

// ---------------------------------------------------------------------------
// HMMA flash attention.  CTA = (b, h, 128-row Q tile).  256 threads, 8 warps,
// warp = 16 Q rows x full 128 cols.  Q' resident in smem; K'/V' streamed.
// ---------------------------------------------------------------------------
#define AT_QROWB 784                       // Q' smem row stride (768 data + 16)
#define AT_PROWB 272                       // P smem row stride (256 data + 16)
#define AT_KSTG  10240                     // 128 rows x 80B
#define SQ_OFF   0
#define SPH_OFF  (128 * AT_QROWB)          // 100352
#define SPL_OFF  (SPH_OFF + 128 * AT_PROWB)
#define SKV_OFF  (SPL_OFF + 128 * AT_PROWB)
#define ATT_SMEM (SKV_OFF + 3 * AT_KSTG)   // 200704

__global__ __launch_bounds__(256, 1) void attn_mma()
{
    extern __shared__ char smraw[];
    const uint32_t sb0 = smem_u32(smraw);

    const int tid  = threadIdx.x;
    const int lane = tid & 31;
    const int w    = tid >> 5;
    const int qi   = 15 - (int)blockIdx.x;    // big tiles first
    const int h    = blockIdx.y;
    const int b    = blockIdx.z;
    const int kvh  = h >> 2;

    const __nv_bfloat16* Qg  = g_Qe + ((size_t)(b * NH + h) * T_ + qi * 128) * 384;
    const __nv_bfloat16* Kg  = g_Ke + ((size_t)(b * NKV + kvh) * T_) * 384;
    const __nv_bfloat16* Vhg = g_Vth + (size_t)(b * NKV + kvh) * HD * T_;
    const __nv_bfloat16* Vlg = g_Vtl + (size_t)(b * NKV + kvh) * HD * T_;

    // ---- load resident Q' tile (128 x 384 bf16) ----
    {
        const int row = tid >> 1, half = tid & 1;
#pragma unroll
        for (int jj = 0; jj < 24; jj++) {
            const int c16 = half * 24 + jj;
            CP_ASYNC16(sb0 + SQ_OFF + (uint32_t)(row * AT_QROWB + c16 * 16),
                       Qg + (size_t)row * 384 + c16 * 8);
        }
        CP_COMMIT();
    }

    auto load_k = [&](int j, int c, int st) {
#pragma unroll
        for (int jj = 0; jj < 2; jj++) {
            const int p   = tid + (jj << 8);
            const int row = p >> 2;
            const int c16 = p & 3;
            CP_ASYNC16(sb0 + SKV_OFF + st * AT_KSTG + (uint32_t)(row * 80 + c16 * 16),
                       Kg + (size_t)(j * 128 + row) * 384 + c * 32 + c16 * 8);
        }
        CP_COMMIT();
    };
    auto load_v = [&](int j, int c, int st) {
        const int pass = c >> 2, q = c & 3;
        const __nv_bfloat16* Vg = (pass == 1) ? Vlg : Vhg;
#pragma unroll
        for (int jj = 0; jj < 2; jj++) {
            const int p   = tid + (jj << 8);
            const int row = p >> 2;
            const int c16 = p & 3;
            CP_ASYNC16(sb0 + SKV_OFF + st * AT_KSTG + (uint32_t)(row * 80 + c16 * 16),
                       Vg + (size_t)row * T_ + j * 128 + q * 32 + c16 * 8);
        }
        CP_COMMIT();
    };

    float o[16][4];
#pragma unroll
    for (int n = 0; n < 16; n++)
#pragma unroll
        for (int x = 0; x < 4; x++) o[n][x] = 0.f;
    float m0 = -1e30f, m1 = -1e30f, l0 = 0.f, l1 = 0.f;

    const uint32_t lm80    = (uint32_t)((lane & 15) * 80 + (lane >> 4) * 16);
    const uint32_t aq_base = sb0 + SQ_OFF + (uint32_t)((w * 16 + (lane & 15)) * AT_QROWB + (lane >> 4) * 16);
    const uint32_t ap_row  = (uint32_t)((w * 16 + (lane & 15)) * AT_PROWB + (lane >> 4) * 16);
    const int rloc0 = w * 16 + (lane >> 2);           // local row (first)
    const int cbase = (lane & 3) * 2;

    for (int j = 0; j <= qi; j++) {
        // ================= QK phase =================
        load_k(j, 0, 0);
        load_k(j, 1, 1);

        float s[16][4];
#pragma unroll
        for (int n = 0; n < 16; n++)
#pragma unroll
            for (int x = 0; x < 4; x++) s[n][x] = 0.f;

        for (int i = 0; i < 12; i++) {
            if (i == 11) { CP_WAIT(0); } else { CP_WAIT(1); }
            __syncthreads();
            if (i + 2 < 12) load_k(j, i + 2, (i + 2) % 3);

            const uint32_t sbK = sb0 + SKV_OFF + (i % 3) * AT_KSTG;
#pragma unroll
            for (int ks = 0; ks < 2; ks++) {
                uint32_t af[4];
                LDMATRIX_X4(af[0], af[1], af[2], af[3],
                            aq_base + (uint32_t)(i * 64 + ks * 32));
                uint32_t bfr[8][4];
#pragma unroll
                for (int p = 0; p < 8; p++)
                    LDMATRIX_X4(bfr[p][0], bfr[p][1], bfr[p][2], bfr[p][3],
                                sbK + (uint32_t)(p * 16 * 80) + lm80 + (uint32_t)(ks * 32));
#pragma unroll
                for (int p = 0; p < 8; p++) {
                    MMA_BF16(s[2 * p],     af, bfr[p][0], bfr[p][2]);
                    MMA_BF16(s[2 * p + 1], af, bfr[p][1], bfr[p][3]);
                }
            }
        }

        // ---- causal mask (diagonal block) ----
        if (j == qi) {
#pragma unroll
            for (int n = 0; n < 16; n++) {
                const int col = n * 8 + cbase;
#pragma unroll
                for (int x = 0; x < 4; x++) {
                    const int cc = col + (x & 1);
                    const int rr = rloc0 + ((x >> 1) << 3);
                    if (cc > rr) s[n][x] = -1e30f;
                }
            }
        }

        // ---- prefetch first PV chunks (overlap with softmax) ----
        load_v(j, 0, 0);
        load_v(j, 1, 1);

        // ---- online softmax (rows warp-local; quad = same row pair) ----
        float mx0 = -1e30f, mx1 = -1e30f;
#pragma unroll
        for (int n = 0; n < 16; n++) {
            mx0 = fmaxf(mx0, fmaxf(s[n][0], s[n][1]));
            mx1 = fmaxf(mx1, fmaxf(s[n][2], s[n][3]));
        }
        mx0 = fmaxf(mx0, __shfl_xor_sync(0xffffffffu, mx0, 1));
        mx0 = fmaxf(mx0, __shfl_xor_sync(0xffffffffu, mx0, 2));
        mx1 = fmaxf(mx1, __shfl_xor_sync(0xffffffffu, mx1, 1));
        mx1 = fmaxf(mx1, __shfl_xor_sync(0xffffffffu, mx1, 2));

        const float mn0 = fmaxf(m0, mx0), mn1 = fmaxf(m1, mx1);
        const float a0 = exp2f(m0 - mn0), a1 = exp2f(m1 - mn1);
        m0 = mn0; m1 = mn1;

        float sum0 = 0.f, sum1 = 0.f;
        char* smc = smraw;
#pragma unroll
        for (int n = 0; n < 16; n++) {
            const float p0 = exp2f(s[n][0] - mn0);
            const float p1 = exp2f(s[n][1] - mn0);
            const float p2 = exp2f(s[n][2] - mn1);
            const float p3 = exp2f(s[n][3] - mn1);
            sum0 += p0 + p1;
            sum1 += p2 + p3;
            const __nv_bfloat16 h0 = __float2bfloat16(p0), h1b = __float2bfloat16(p1);
            const __nv_bfloat16 h2 = __float2bfloat16(p2), h3b = __float2bfloat16(p3);
            const int colb = (n * 8 + cbase) * 2;
            const int ra = w * 16 + (lane >> 2);
            *(__nv_bfloat162*)(smc + SPH_OFF + ra * AT_PROWB + colb) =
                __nv_bfloat162(h0, h1b);
            *(__nv_bfloat162*)(smc + SPH_OFF + (ra + 8) * AT_PROWB + colb) =
                __nv_bfloat162(h2, h3b);
            *(__nv_bfloat162*)(smc + SPL_OFF + ra * AT_PROWB + colb) =
                __nv_bfloat162(__float2bfloat16(p0 - __bfloat162float(h0)),
                               __float2bfloat16(p1 - __bfloat162float(h1b)));
            *(__nv_bfloat162*)(smc + SPL_OFF + (ra + 8) * AT_PROWB + colb) =
                __nv_bfloat162(__float2bfloat16(p2 - __bfloat162float(h2)),
                               __float2bfloat16(p3 - __bfloat162float(h3b)));
        }
        sum0 += __shfl_xor_sync(0xffffffffu, sum0, 1);
        sum0 += __shfl_xor_sync(0xffffffffu, sum0, 2);
        sum1 += __shfl_xor_sync(0xffffffffu, sum1, 1);
        sum1 += __shfl_xor_sync(0xffffffffu, sum1, 2);
        l0 = l0 * a0 + sum0;
        l1 = l1 * a1 + sum1;

#pragma unroll
        for (int n = 0; n < 16; n++) {
            o[n][0] *= a0; o[n][1] *= a0; o[n][2] *= a1; o[n][3] *= a1;
        }

        // ================= PV phase =================
        for (int c = 0; c < 12; c++) {
            if (c == 11) { CP_WAIT(0); } else { CP_WAIT(1); }
            __syncthreads();
            if (c + 2 < 12) load_v(j, c + 2, (c + 2) % 3);

            const int pass = c >> 2, q = c & 3;
            const uint32_t abase = sb0 + ((pass == 2) ? SPL_OFF : SPH_OFF) + ap_row
                                 + (uint32_t)(q * 64);
            const uint32_t sbV = sb0 + SKV_OFF + (c % 3) * AT_KSTG;
#pragma unroll
            for (int ks = 0; ks < 2; ks++) {
                uint32_t af[4];
                LDMATRIX_X4(af[0], af[1], af[2], af[3], abase + (uint32_t)(ks * 32));
                uint32_t bfr[8][4];
#pragma unroll
                for (int p = 0; p < 8; p++)
                    LDMATRIX_X4(bfr[p][0], bfr[p][1], bfr[p][2], bfr[p][3],
                                sbV + (uint32_t)(p * 16 * 80) + lm80 + (uint32_t)(ks * 32));
#pragma unroll
                for (int p = 0; p < 8; p++) {
                    MMA_BF16(o[2 * p],     af, bfr[p][0], bfr[p][2]);
                    MMA_BF16(o[2 * p + 1], af, bfr[p][1], bfr[p][3]);
                }
            }
        }
    }

    // ---- final normalize + store ----
    const float il0 = 1.f / l0, il1 = 1.f / l1;
    const int grow0 = qi * 128 + rloc0;
#pragma unroll
    for (int n = 0; n < 16; n++) {
        const int col = n * 8 + cbase;
        *(float2*)(g_O + (size_t)(b * T_ + grow0) * D_ + h * HD + col) =
            make_float2(o[n][0] * il0, o[n][1] * il0);
        *(float2*)(g_O + (size_t)(b * T_ + grow0 + 8) * D_ + h * HD + col) =
            make_float2(o[n][2] * il1, o[n][3] * il1);
    }
}

// ---------------------------------------------------------------------------
extern "C" void kernel_launch(void* const* d_in, const int* in_sizes, int n_in,
                              void* d_out, int out_size)
{
    const float* x  = (const float*)d_in[0];
    const float* Wq = (const float*)d_in[1];
    const float* Wk = (const float*)d_in[2];
    const float* Wv = (const float*)d_in[3];
    const float* Wo = (const float*)d_in[4];
    float* out = (float*)d_out;

    float *Qb, *Kb, *Vb, *Ob;
    __nv_bfloat16 *AE, *WQE, *WKE, *WVE, *WOE;
    cudaGetSymbolAddress((void**)&Qb, g_Q);
    cudaGetSymbolAddress((void**)&Kb, g_K);
    cudaGetSymbolAddress((void**)&Vb, g_V);
    cudaGetSymbolAddress((void**)&Ob, g_O);
    cudaGetSymbolAddress((void**)&AE, g_AE);
    cudaGetSymbolAddress((void**)&WQE, g_WQE);
    cudaGetSymbolAddress((void**)&WKE, g_WKE);
    cudaGetSymbolAddress((void**)&WVE, g_WVE);
    cudaGetSymbolAddress((void**)&WOE, g_WOE);

    const int M = B_ * T_;  // 8192

    cudaFuncSetAttribute(gemm_bf16_nt, cudaFuncAttributeMaxDynamicSharedMemorySize,
                         GEMM_SMEM);
    cudaFuncSetAttribute(attn_mma, cudaFuncAttributeMaxDynamicSharedMemorySize,
                         ATT_SMEM);

    // split conversions for projections
    split_kernel<<<4096, 256>>>(x,  AE,  D_, 0, (size_t)M * D_);
    split_kernel<<<2048, 256>>>(Wq, WQE, D_, 1, (size_t)D_ * D_);
    split_kernel<<<1024, 256>>>(Wk, WKE, D_, 1, (size_t)KVD * D_);
    split_kernel<<<1024, 256>>>(Wv, WVE, D_, 1, (size_t)KVD * D_);
    split_kernel<<<2048, 256>>>(Wo, WOE, D_, 1, (size_t)D_ * D_);

    // projections on tensor cores (HMMA)
    gemm_bf16_nt<<<dim3(D_ / 128, M / 128), 256, GEMM_SMEM>>>(AE, WQE, Qb, D_, KP);
    gemm_bf16_nt<<<dim3(KVD / 128, M / 128), 256, GEMM_SMEM>>>(AE, WKE, Kb, KVD, KP);
    gemm_bf16_nt<<<dim3(KVD / 128, M / 128), 256, GEMM_SMEM>>>(AE, WVE, Vb, KVD, KP);

    // attention operand prep
    rope_split_kernel<<<dim3(T_, B_), 256>>>();
    v_split_kernel<<<dim3(T_ / 256, HD, B_ * NKV), 256>>>();

    // tensor-core flash attention
    attn_mma<<<dim3(T_ / 128, NH, B_), 256, ATT_SMEM>>>();

    // output projection
    split_kernel<<<4096, 256>>>(Ob, AE, D_, 0, (size_t)M * D_);
    gemm_bf16_nt<<<dim3(D_ / 128, M / 128), 256, GEMM_SMEM>>>(AE, WOE, out, D_, KP);
}

// round 5
// speedup vs baseline: 7.9630x; 1.1245x over previous
#include <cuda_runtime.h>
#include <cuda_bf16.h>
#include <math.h>
#include <stdint.h>

#define B_   4
#define T_   2048
#define D_   2048
#define NH   16
#define NKV  4
#define HD   128
#define KVD  (NKV*HD)   // 512
#define KP   (3*D_)     // 6144 split-expanded K for projections

// 1/sqrt(hd) * log2(e), folded into Q split
#define SCALE_LOG2E 0.1275174277208884f

// ---------------- scratch (__device__ globals; allocation-free rule) -------
__device__ float g_Q[(size_t)B_ * T_ * D_];
__device__ float g_K[(size_t)B_ * T_ * KVD];
__device__ float g_V[(size_t)B_ * T_ * KVD];

__device__ __nv_bfloat16 g_AE [(size_t)(B_*T_) * KP];   // x-expand / attn-out-expand
__device__ __nv_bfloat16 g_WQE[(size_t)D_  * KP];
__device__ __nv_bfloat16 g_WKE[(size_t)KVD * KP];
__device__ __nv_bfloat16 g_WVE[(size_t)KVD * KP];
__device__ __nv_bfloat16 g_WOE[(size_t)D_  * KP];

// attention split operands: [Qh|Ql], [Kh|Kl] (256 cols each)
__device__ __nv_bfloat16 g_Qe [(size_t)B_ * NH  * T_ * 256];
__device__ __nv_bfloat16 g_Ke [(size_t)B_ * NKV * T_ * 256];
__device__ __nv_bfloat16 g_Vth[(size_t)B_ * NKV * HD * T_];   // [b,kvh,d,t] hi
__device__ __nv_bfloat16 g_Vtl[(size_t)B_ * NKV * HD * T_];   // lo

// ---------------- helpers --------------------------------------------------
__device__ __forceinline__ uint32_t smem_u32(const void* p) {
    uint32_t a;
    asm("{ .reg .u64 t; cvta.to.shared.u64 t, %1; cvt.u32.u64 %0, t; }" : "=r"(a) : "l"(p));
    return a;
}
#define CP_ASYNC16(dst, src) \
    asm volatile("cp.async.cg.shared.global [%0], [%1], 16;" :: "r"(dst), "l"(src) : "memory")
#define CP_COMMIT() asm volatile("cp.async.commit_group;" ::: "memory")
#define CP_WAIT(N)  asm volatile("cp.async.wait_group %0;" :: "n"(N) : "memory")

#define LDMATRIX_X4(r0, r1, r2, r3, addr) \
    asm volatile("ldmatrix.sync.aligned.m8n8.x4.shared.b16 {%0,%1,%2,%3}, [%4];" \
        : "=r"(r0), "=r"(r1), "=r"(r2), "=r"(r3) : "r"(addr))

#define MMA_BF16(d, a, b0, b1) \
    asm volatile("mma.sync.aligned.m16n8k16.row.col.f32.bf16.bf16.f32 " \
        "{%0,%1,%2,%3}, {%4,%5,%6,%7}, {%8,%9}, {%0,%1,%2,%3};" \
        : "+f"((d)[0]), "+f"((d)[1]), "+f"((d)[2]), "+f"((d)[3]) \
        : "r"((a)[0]), "r"((a)[1]), "r"((a)[2]), "r"((a)[3]), "r"(b0), "r"(b1))

// ---------------------------------------------------------------------------
// split conversion: fp32 [M,K] -> bf16 [M,3K]
// bmode=0: [hi | hi | lo]    bmode=1: [hi | lo | hi]
// ---------------------------------------------------------------------------
__global__ void split_kernel(const float* __restrict__ in, __nv_bfloat16* __restrict__ out,
                             int K, int bmode, size_t total)
{
    for (size_t e = (size_t)blockIdx.x * blockDim.x + threadIdx.x; e < total;
         e += (size_t)gridDim.x * blockDim.x) {
        size_t m = e / (size_t)K;
        int k = (int)(e - m * (size_t)K);
        float v = in[e];
        __nv_bfloat16 hi = __float2bfloat16(v);
        __nv_bfloat16 lo = __float2bfloat16(v - __bfloat162float(hi));
        __nv_bfloat16* row = out + m * (size_t)(3 * K);
        row[k]         = hi;
        row[K + k]     = bmode ? lo : hi;
        row[2 * K + k] = bmode ? hi : lo;
    }
}

// ---------------------------------------------------------------------------
// HMMA bf16 NT GEMM.  Tile 128x128, BK=64, 256 thr (8 warps 4m x 2n),
// 3-stage cp.async, padded stride 144B.
// ---------------------------------------------------------------------------
#define GBK        64
#define G_STRIDE_B 144
#define G_TILE_B   (128 * G_STRIDE_B)          // 18432
#define G_NSTAGE   3
#define GEMM_SMEM  (G_NSTAGE * 2 * G_TILE_B)   // 110592

__global__ __launch_bounds__(256, 2)
void gemm_bf16_nt(const __nv_bfloat16* __restrict__ A, const __nv_bfloat16* __restrict__ B,
                  float* __restrict__ C, int N, int Kp)
{
    extern __shared__ char smraw[];
    const uint32_t smem = smem_u32(smraw);

    const int tid    = threadIdx.x;
    const int lane   = tid & 31;
    const int wid    = tid >> 5;
    const int warp_m = wid & 3;
    const int warp_n = wid >> 2;

    const __nv_bfloat16* Ag = A + (size_t)blockIdx.y * 128 * Kp;
    const __nv_bfloat16* Bg = B + (size_t)blockIdx.x * 128 * Kp;
    const int nch = Kp / GBK;

    auto load_chunk = [&](int chunk, int buf) {
        const uint32_t sa = smem + buf * 2 * G_TILE_B;
        const uint32_t sb = sa + G_TILE_B;
        const int k0 = chunk * GBK;
#pragma unroll
        for (int j = 0; j < 4; j++) {
            const int p   = tid + (j << 8);       // 0..1023
            const int row = p >> 3;
            const int c16 = p & 7;
            const uint32_t off = (uint32_t)(row * G_STRIDE_B + c16 * 16);
            const size_t gsrc = (size_t)row * Kp + k0 + c16 * 8;
            CP_ASYNC16(sa + off, Ag + gsrc);
            CP_ASYNC16(sb + off, Bg + gsrc);
        }
        CP_COMMIT();
    };

    float acc[2][8][4];
#pragma unroll
    for (int t = 0; t < 2; t++)
#pragma unroll
        for (int n = 0; n < 8; n++)
#pragma unroll
            for (int x = 0; x < 4; x++) acc[t][n][x] = 0.f;

    load_chunk(0, 0);
    load_chunk(1, 1);

    const uint32_t lm_row = (uint32_t)((lane & 15) * G_STRIDE_B + (lane >> 4) * 16);
    const uint32_t a_off  = (uint32_t)(warp_m * 32 * G_STRIDE_B) + lm_row;
    const uint32_t b_off  = (uint32_t)(warp_n * 64 * G_STRIDE_B) + lm_row;

    for (int i = 0; i < nch; i++) {
        if (i == nch - 1) { CP_WAIT(0); } else { CP_WAIT(1); }
        __syncthreads();
        if (i + 2 < nch) load_chunk(i + 2, (i + 2) % G_NSTAGE);

        const uint32_t sa = smem + (i % G_NSTAGE) * 2 * G_TILE_B;
        const uint32_t sb = sa + G_TILE_B;
#pragma unroll
        for (int s = 0; s < 4; s++) {
            const uint32_t ks = (uint32_t)(s * 32);
            uint32_t af[2][4];
#pragma unroll
            for (int t = 0; t < 2; t++)
                LDMATRIX_X4(af[t][0], af[t][1], af[t][2], af[t][3],
                            sa + a_off + (uint32_t)(t * 16 * G_STRIDE_B) + ks);
            uint32_t bfr[4][4];
#pragma unroll
            for (int p = 0; p < 4; p++)
                LDMATRIX_X4(bfr[p][0], bfr[p][1], bfr[p][2], bfr[p][3],
                            sb + b_off + (uint32_t)(p * 16 * G_STRIDE_B) + ks);
#pragma unroll
            for (int t = 0; t < 2; t++)
#pragma unroll
                for (int p = 0; p < 4; p++) {
                    MMA_BF16(acc[t][2 * p],     af[t], bfr[p][0], bfr[p][2]);
                    MMA_BF16(acc[t][2 * p + 1], af[t], bfr[p][1], bfr[p][3]);
                }
        }
    }

#pragma unroll
    for (int t = 0; t < 2; t++) {
        const int row0 = blockIdx.y * 128 + warp_m * 32 + t * 16 + (lane >> 2);
#pragma unroll
        for (int n = 0; n < 8; n++) {
            const int col = blockIdx.x * 128 + warp_n * 64 + n * 8 + (lane & 3) * 2;
            *(float2*)(C + (size_t)row0 * N + col) =
                make_float2(acc[t][n][0], acc[t][n][1]);
            *(float2*)(C + (size_t)(row0 + 8) * N + col) =
                make_float2(acc[t][n][2], acc[t][n][3]);
        }
    }
}

// ---------------------------------------------------------------------------
// RoPE + hi/lo split:  Q' = [Qh|Ql] (scaled), K' = [Kh|Kl], 256 cols each.
// ---------------------------------------------------------------------------
__global__ void rope_split_kernel()
{
    const int t = blockIdx.x;
    const int b = blockIdx.y;
    const float LOG2_10000_OVER_64 = 0.20762050593045952f;

    for (int idx = threadIdx.x; idx < NH * 64; idx += blockDim.x) {
        const int head = idx >> 6;
        const int i    = idx & 63;
        const float invf = exp2f(-(float)i * LOG2_10000_OVER_64);
        float s, c;
        sincosf((float)t * invf, &s, &c);
        const float* p = g_Q + ((size_t)(b * T_ + t) * D_ + head * HD);
        float q1 = p[i], q2 = p[i + 64];
        float r1 = (q1 * c - q2 * s) * SCALE_LOG2E;
        float r2 = (q1 * s + q2 * c) * SCALE_LOG2E;
        __nv_bfloat16 h1 = __float2bfloat16(r1);
        __nv_bfloat16 h2 = __float2bfloat16(r2);
        __nv_bfloat16* row = g_Qe + ((size_t)(b * NH + head) * T_ + t) * 256;
        row[i]       = h1;  row[i + 64]  = h2;
        row[128 + i] = __float2bfloat16(r1 - __bfloat162float(h1));
        row[192 + i] = __float2bfloat16(r2 - __bfloat162float(h2));
    }
    for (int idx = threadIdx.x; idx < NKV * 64; idx += blockDim.x) {
        const int kvh = idx >> 6;
        const int i   = idx & 63;
        const float invf = exp2f(-(float)i * LOG2_10000_OVER_64);
        float s, c;
        sincosf((float)t * invf, &s, &c);
        const float* p = g_K + ((size_t)(b * T_ + t) * KVD + kvh * HD);
        float q1 = p[i], q2 = p[i + 64];
        float r1 = q1 * c - q2 * s;
        float r2 = q1 * s + q2 * c;
        __nv_bfloat16 h1 = __float2bfloat16(r1);
        __nv_bfloat16 h2 = __float2bfloat16(r2);
        __nv_bfloat16* row = g_Ke + ((size_t)(b * NKV + kvh) * T_ + t) * 256;
        row[i]       = h1;  row[i + 64]  = h2;
        row[128 + i] = __float2bfloat16(r1 - __bfloat162float(h1));
        row[192 + i] = __float2bfloat16(r2 - __bfloat162float(h2));
    }
}

// V transpose + split:  g_V [b,t,kvh,d] fp32 -> g_Vth/g_Vtl [b,kvh,d,t] bf16
__global__ void v_split_kernel()
{
    const int t   = blockIdx.x * blockDim.x + threadIdx.x;
    const int d   = blockIdx.y;
    const int bz  = blockIdx.z;
    const int b   = bz >> 2, kvh = bz & 3;
    const float v = g_V[(size_t)(b * T_ + t) * KVD + kvh * HD + d];
    __nv_bfloat16 hi = __float2bfloat16(v);
    __nv_bfloat16 lo = __float2bfloat16(v - __bfloat162float(hi));
    const size_t o = ((size_t)bz * HD + d) * T_ + t;
    g_Vth[o] = hi;
    g_Vtl[o] = lo;
}

// ---------------------------------------------------------------------------
// HMMA flash attention with plane reuse.  CTA = (b, h, 128 Q rows), 256 thr,
// warp = 16 rows x 128 cols.  8 K-chunks/phase (Kh x {Qh,Ql}, Kl x Qh),
// 8 V-chunks/phase (Vh x {Ph,Pl}, Vl x Ph).  5-stage cp.async pipeline.
// Epilogue writes hi/hi/lo bf16 straight into g_AE.
// ---------------------------------------------------------------------------
#define AT_QROWB 528                       // 256 bf16 + 16B pad
#define AT_PROWB 272                       // 128 bf16 + 16B pad
#define AT_KSTG  10240                     // 128 rows x 80B
#define AT_NSTG  5
#define SQ_OFF   0
#define SPH_OFF  (128 * AT_QROWB)                  // 67584
#define SPL_OFF  (SPH_OFF + 128 * AT_PROWB)        // 102400
#define SKV_OFF  (SPL_OFF + 128 * AT_PROWB)        // 137216
#define ATT_SMEM (SKV_OFF + AT_NSTG * AT_KSTG)     // 188416

__global__ __launch_bounds__(256, 1) void attn_mma()
{
    extern __shared__ char smraw[];
    const uint32_t sb0 = smem_u32(smraw);

    const int tid  = threadIdx.x;
    const int lane = tid & 31;
    const int w    = tid >> 5;
    const int qi   = 15 - (int)blockIdx.x;    // big tiles first
    const int h    = blockIdx.y;
    const int b    = blockIdx.z;
    const int kvh  = h >> 2;

    const __nv_bfloat16* Qg  = g_Qe + ((size_t)(b * NH + h) * T_ + qi * 128) * 256;
    const __nv_bfloat16* Kg  = g_Ke + ((size_t)(b * NKV + kvh) * T_) * 256;
    const __nv_bfloat16* Vhg = g_Vth + (size_t)(b * NKV + kvh) * HD * T_;
    const __nv_bfloat16* Vlg = g_Vtl + (size_t)(b * NKV + kvh) * HD * T_;

    // resident Q' tile (128 x 256 bf16): 16 x cp.16 per thread
    {
        const int row = tid >> 1, half = tid & 1;
#pragma unroll
        for (int jj = 0; jj < 16; jj++) {
            const int c16 = half * 16 + jj;
            CP_ASYNC16(sb0 + SQ_OFF + (uint32_t)(row * AT_QROWB + c16 * 16),
                       Qg + (size_t)row * 256 + c16 * 8);
        }
        CP_COMMIT();
    }

    auto load_k = [&](int j, int c, int st) {
#pragma unroll
        for (int jj = 0; jj < 2; jj++) {
            const int p   = tid + (jj << 8);
            const int row = p >> 2;
            const int c16 = p & 3;
            CP_ASYNC16(sb0 + SKV_OFF + st * AT_KSTG + (uint32_t)(row * 80 + c16 * 16),
                       Kg + (size_t)(j * 128 + row) * 256 + c * 32 + c16 * 8);
        }
        CP_COMMIT();
    };
    auto load_v = [&](int j, int c, int st) {
        const __nv_bfloat16* Vg = (c < 4) ? Vhg : Vlg;
        const int toff = j * 128 + ((c < 4) ? c : c - 4) * 32;
#pragma unroll
        for (int jj = 0; jj < 2; jj++) {
            const int p   = tid + (jj << 8);
            const int row = p >> 2;
            const int c16 = p & 3;
            CP_ASYNC16(sb0 + SKV_OFF + st * AT_KSTG + (uint32_t)(row * 80 + c16 * 16),
                       Vg + (size_t)row * T_ + toff + c16 * 8);
        }
        CP_COMMIT();
    };

    float o[16][4];
#pragma unroll
    for (int n = 0; n < 16; n++)
#pragma unroll
        for (int x = 0; x < 4; x++) o[n][x] = 0.f;
    float m0 = -1e30f, m1 = -1e30f, l0 = 0.f, l1 = 0.f;

    const uint32_t lm80    = (uint32_t)((lane & 15) * 80 + (lane >> 4) * 16);
    const uint32_t aq_base = sb0 + SQ_OFF + (uint32_t)((w * 16 + (lane & 15)) * AT_QROWB + (lane >> 4) * 16);
    const uint32_t ap_row  = (uint32_t)((w * 16 + (lane & 15)) * AT_PROWB + (lane >> 4) * 16);
    const int rloc0 = w * 16 + (lane >> 2);
    const int cbase = (lane & 3) * 2;

    for (int j = 0; j <= qi; j++) {
        // ================= QK phase =================
        __syncthreads();                     // protect last V bufs of prev j
        load_k(j, 0, 0); load_k(j, 1, 1); load_k(j, 2, 2); load_k(j, 3, 3);

        float s[16][4];
#pragma unroll
        for (int n = 0; n < 16; n++)
#pragma unroll
            for (int x = 0; x < 4; x++) s[n][x] = 0.f;

#pragma unroll
        for (int c = 0; c < 8; c++) {
            if (c < 5)      { CP_WAIT(3); }
            else if (c == 5){ CP_WAIT(2); }
            else if (c == 6){ CP_WAIT(1); }
            else            { CP_WAIT(0); }
            __syncthreads();
            if (c + 4 < 8) load_k(j, c + 4, (c + 4) % AT_NSTG);

            const uint32_t sbK = sb0 + SKV_OFF + (c % AT_NSTG) * AT_KSTG;
            const uint32_t asl = (uint32_t)(((c < 4) ? c : c - 4) * 64);
#pragma unroll
            for (int ks = 0; ks < 2; ks++) {
                const uint32_t ko = (uint32_t)(ks * 32);
                uint32_t bfr[8][4];
#pragma unroll
                for (int p = 0; p < 8; p++)
                    LDMATRIX_X4(bfr[p][0], bfr[p][1], bfr[p][2], bfr[p][3],
                                sbK + (uint32_t)(p * 16 * 80) + lm80 + ko);
                uint32_t af[4];
                LDMATRIX_X4(af[0], af[1], af[2], af[3], aq_base + asl + ko);
#pragma unroll
                for (int p = 0; p < 8; p++) {
                    MMA_BF16(s[2 * p],     af, bfr[p][0], bfr[p][2]);
                    MMA_BF16(s[2 * p + 1], af, bfr[p][1], bfr[p][3]);
                }
                if (c < 4) {   // Kh also pairs with Ql
                    uint32_t ag[4];
                    LDMATRIX_X4(ag[0], ag[1], ag[2], ag[3], aq_base + 256u + asl + ko);
#pragma unroll
                    for (int p = 0; p < 8; p++) {
                        MMA_BF16(s[2 * p],     ag, bfr[p][0], bfr[p][2]);
                        MMA_BF16(s[2 * p + 1], ag, bfr[p][1], bfr[p][3]);
                    }
                }
            }
        }

        // ---- V prefetch (bufs 0..3 free after this sync) ----
        __syncthreads();
        load_v(j, 0, 0); load_v(j, 1, 1); load_v(j, 2, 2); load_v(j, 3, 3);

        // ---- causal mask (diagonal block) ----
        if (j == qi) {
#pragma unroll
            for (int n = 0; n < 16; n++) {
                const int col = n * 8 + cbase;
#pragma unroll
                for (int x = 0; x < 4; x++) {
                    const int cc = col + (x & 1);
                    const int rr = rloc0 + ((x >> 1) << 3);
                    if (cc > rr) s[n][x] = -1e30f;
                }
            }
        }

        // ---- online softmax (quad-local rows) ----
        float mx0 = -1e30f, mx1 = -1e30f;
#pragma unroll
        for (int n = 0; n < 16; n++) {
            mx0 = fmaxf(mx0, fmaxf(s[n][0], s[n][1]));
            mx1 = fmaxf(mx1, fmaxf(s[n][2], s[n][3]));
        }
        mx0 = fmaxf(mx0, __shfl_xor_sync(0xffffffffu, mx0, 1));
        mx0 = fmaxf(mx0, __shfl_xor_sync(0xffffffffu, mx0, 2));
        mx1 = fmaxf(mx1, __shfl_xor_sync(0xffffffffu, mx1, 1));
        mx1 = fmaxf(mx1, __shfl_xor_sync(0xffffffffu, mx1, 2));

        const float mn0 = fmaxf(m0, mx0), mn1 = fmaxf(m1, mx1);
        const float a0 = exp2f(m0 - mn0), a1 = exp2f(m1 - mn1);
        m0 = mn0; m1 = mn1;

        float sum0 = 0.f, sum1 = 0.f;
        char* smc = smraw;
#pragma unroll
        for (int n = 0; n < 16; n++) {
            const float p0 = exp2f(s[n][0] - mn0);
            const float p1 = exp2f(s[n][1] - mn0);
            const float p2 = exp2f(s[n][2] - mn1);
            const float p3 = exp2f(s[n][3] - mn1);
            sum0 += p0 + p1;
            sum1 += p2 + p3;
            const __nv_bfloat16 h0 = __float2bfloat16(p0), h1b = __float2bfloat16(p1);
            const __nv_bfloat16 h2 = __float2bfloat16(p2), h3b = __float2bfloat16(p3);
            const int colb = (n * 8 + cbase) * 2;
            const int ra = w * 16 + (lane >> 2);
            *(__nv_bfloat162*)(smc + SPH_OFF + ra * AT_PROWB + colb) =
                __nv_bfloat162(h0, h1b);
            *(__nv_bfloat162*)(smc + SPH_OFF + (ra + 8) * AT_PROWB + colb) =
                __nv_bfloat162(h2, h3b);
            *(__nv_bfloat162*)(smc + SPL_OFF + ra * AT_PROWB + colb) =
                __nv_bfloat162(__float2bfloat16(p0 - __bfloat162float(h0)),
                               __float2bfloat16(p1 - __bfloat162float(h1b)));
            *(__nv_bfloat162*)(smc + SPL_OFF + (ra + 8) * AT_PROWB + colb) =
                __nv_bfloat162(__float2bfloat16(p2 - __bfloat162float(h2)),
                               __float2bfloat16(p3 - __bfloat162float(h3b)));
        }
        sum0 += __shfl_xor_sync(0xffffffffu, sum0, 1);
        sum0 += __shfl_xor_sync(0xffffffffu, sum0, 2);
        sum1 += __shfl_xor_sync(0xffffffffu, sum1, 1);
        sum1 += __shfl_xor_sync(0xffffffffu, sum1, 2);
        l0 = l0 * a0 + sum0;
        l1 = l1 * a1 + sum1;

#pragma unroll
        for (int n = 0; n < 16; n++) {
            o[n][0] *= a0; o[n][1] *= a0; o[n][2] *= a1; o[n][3] *= a1;
        }

        // ================= PV phase =================
#pragma unroll
        for (int c = 0; c < 8; c++) {
            if (c < 5)      { CP_WAIT(3); }
            else if (c == 5){ CP_WAIT(2); }
            else if (c == 6){ CP_WAIT(1); }
            else            { CP_WAIT(0); }
            __syncthreads();
            if (c + 4 < 8) load_v(j, c + 4, (c + 4) % AT_NSTG);

            const uint32_t sbV = sb0 + SKV_OFF + (c % AT_NSTG) * AT_KSTG;
            const uint32_t asl = (uint32_t)(((c < 4) ? c : c - 4) * 64);
#pragma unroll
            for (int ks = 0; ks < 2; ks++) {
                const uint32_t ko = (uint32_t)(ks * 32);
                uint32_t bfr[8][4];
#pragma unroll
                for (int p = 0; p < 8; p++)
                    LDMATRIX_X4(bfr[p][0], bfr[p][1], bfr[p][2], bfr[p][3],
                                sbV + (uint32_t)(p * 16 * 80) + lm80 + ko);
                uint32_t af[4];
                LDMATRIX_X4(af[0], af[1], af[2], af[3],
                            sb0 + SPH_OFF + ap_row + asl + ko);
#pragma unroll
                for (int p = 0; p < 8; p++) {
                    MMA_BF16(o[2 * p],     af, bfr[p][0], bfr[p][2]);
                    MMA_BF16(o[2 * p + 1], af, bfr[p][1], bfr[p][3]);
                }
                if (c < 4) {   // Vh also pairs with Pl
                    uint32_t ag[4];
                    LDMATRIX_X4(ag[0], ag[1], ag[2], ag[3],
                                sb0 + SPL_OFF + ap_row + asl + ko);
#pragma unroll
                    for (int p = 0; p < 8; p++) {
                        MMA_BF16(o[2 * p],     ag, bfr[p][0], bfr[p][2]);
                        MMA_BF16(o[2 * p + 1], ag, bfr[p][1], bfr[p][3]);
                    }
                }
            }
        }
    }

    // ---- epilogue: normalize + hi/hi/lo split straight into g_AE ----
    const float il0 = 1.f / l0, il1 = 1.f / l1;
    const int grow0 = qi * 128 + rloc0;
    __nv_bfloat16* r0 = g_AE + (size_t)(b * T_ + grow0) * KP;
    __nv_bfloat16* r1 = g_AE + (size_t)(b * T_ + grow0 + 8) * KP;
#pragma unroll
    for (int n = 0; n < 16; n++) {
        const int col = h * HD + n * 8 + cbase;
        float v0 = o[n][0] * il0, v1 = o[n][1] * il0;
        float v2 = o[n][2] * il1, v3 = o[n][3] * il1;
        __nv_bfloat16 a = __float2bfloat16(v0), bb = __float2bfloat16(v1);
        __nv_bfloat16 cc = __float2bfloat16(v2), dd = __float2bfloat16(v3);
        *(__nv_bfloat162*)(r0 + col)          = __nv_bfloat162(a, bb);
        *(__nv_bfloat162*)(r0 + D_ + col)     = __nv_bfloat162(a, bb);
        *(__nv_bfloat162*)(r0 + 2 * D_ + col) =
            __nv_bfloat162(__float2bfloat16(v0 - __bfloat162float(a)),
                           __float2bfloat16(v1 - __bfloat162float(bb)));
        *(__nv_bfloat162*)(r1 + col)          = __nv_bfloat162(cc, dd);
        *(__nv_bfloat162*)(r1 + D_ + col)     = __nv_bfloat162(cc, dd);
        *(__nv_bfloat162*)(r1 + 2 * D_ + col) =
            __nv_bfloat162(__float2bfloat16(v2 - __bfloat162float(cc)),
                           __float2bfloat16(v3 - __bfloat162float(dd)));
    }
}

// ---------------------------------------------------------------------------
extern "C" void kernel_launch(void* const* d_in, const int* in_sizes, int n_in,
                              void* d_out, int out_size)
{
    const float* x  = (const float*)d_in[0];
    const float* Wq = (const float*)d_in[1];
    const float* Wk = (const float*)d_in[2];
    const float* Wv = (const float*)d_in[3];
    const float* Wo = (const float*)d_in[4];
    float* out = (float*)d_out;

    float *Qb, *Kb, *Vb;
    __nv_bfloat16 *AE, *WQE, *WKE, *WVE, *WOE;
    cudaGetSymbolAddress((void**)&Qb, g_Q);
    cudaGetSymbolAddress((void**)&Kb, g_K);
    cudaGetSymbolAddress((void**)&Vb, g_V);
    cudaGetSymbolAddress((void**)&AE, g_AE);
    cudaGetSymbolAddress((void**)&WQE, g_WQE);
    cudaGetSymbolAddress((void**)&WKE, g_WKE);
    cudaGetSymbolAddress((void**)&WVE, g_WVE);
    cudaGetSymbolAddress((void**)&WOE, g_WOE);

    const int M = B_ * T_;  // 8192

    cudaFuncSetAttribute(gemm_bf16_nt, cudaFuncAttributeMaxDynamicSharedMemorySize,
                         GEMM_SMEM);
    cudaFuncSetAttribute(attn_mma, cudaFuncAttributeMaxDynamicSharedMemorySize,
                         ATT_SMEM);

    // split conversions for projections
    split_kernel<<<4096, 256>>>(x,  AE,  D_, 0, (size_t)M * D_);
    split_kernel<<<2048, 256>>>(Wq, WQE, D_, 1, (size_t)D_ * D_);
    split_kernel<<<1024, 256>>>(Wk, WKE, D_, 1, (size_t)KVD * D_);
    split_kernel<<<1024, 256>>>(Wv, WVE, D_, 1, (size_t)KVD * D_);
    split_kernel<<<2048, 256>>>(Wo, WOE, D_, 1, (size_t)D_ * D_);

    // projections on tensor cores (HMMA)
    gemm_bf16_nt<<<dim3(D_ / 128, M / 128), 256, GEMM_SMEM>>>(AE, WQE, Qb, D_, KP);
    gemm_bf16_nt<<<dim3(KVD / 128, M / 128), 256, GEMM_SMEM>>>(AE, WKE, Kb, KVD, KP);
    gemm_bf16_nt<<<dim3(KVD / 128, M / 128), 256, GEMM_SMEM>>>(AE, WVE, Vb, KVD, KP);

    // attention operand prep
    rope_split_kernel<<<dim3(T_, B_), 256>>>();
    v_split_kernel<<<dim3(T_ / 256, HD, B_ * NKV), 256>>>();

    // tensor-core flash attention (writes split output into AE)
    attn_mma<<<dim3(T_ / 128, NH, B_), 256, ATT_SMEM>>>();

    // output projection
    gemm_bf16_nt<<<dim3(D_ / 128, M / 128), 256, GEMM_SMEM>>>(AE, WOE, out, D_, KP);
}

// round 6
// speedup vs baseline: 8.0902x; 1.0160x over previous
#include <cuda_runtime.h>
#include <cuda_bf16.h>
#include <math.h>
#include <stdint.h>

#define B_   4
#define T_   2048
#define D_   2048
#define NH   16
#define NKV  4
#define HD   128
#define KVD  (NKV*HD)   // 512
#define NQKV (D_ + 2*KVD)  // 3072
#define KP   (3*D_)     // 6144 split-expanded K for projections

// 1/sqrt(hd) * log2(e), folded into Q split
#define SCALE_LOG2E 0.1275174277208884f

// ---------------- scratch (__device__ globals; allocation-free rule) -------
__device__ float g_QKV[(size_t)B_ * T_ * NQKV];          // fused projection out

__device__ __nv_bfloat16 g_AE   [(size_t)(B_*T_) * KP];  // x-expand / attn-out-expand
__device__ __nv_bfloat16 g_WQKVE[(size_t)NQKV * KP];     // Wq|Wk|Wv expanded
__device__ __nv_bfloat16 g_WOE  [(size_t)D_   * KP];

// attention split operands: [Qh|Ql], [Kh|Kl] (256 cols each)
__device__ __nv_bfloat16 g_Qe [(size_t)B_ * NH  * T_ * 256];
__device__ __nv_bfloat16 g_Ke [(size_t)B_ * NKV * T_ * 256];
__device__ __nv_bfloat16 g_Vth[(size_t)B_ * NKV * HD * T_];   // [b,kvh,d,t] hi
__device__ __nv_bfloat16 g_Vtl[(size_t)B_ * NKV * HD * T_];   // lo

// ---------------- helpers --------------------------------------------------
__device__ __forceinline__ uint32_t smem_u32(const void* p) {
    uint32_t a;
    asm("{ .reg .u64 t; cvta.to.shared.u64 t, %1; cvt.u32.u64 %0, t; }" : "=r"(a) : "l"(p));
    return a;
}
#define CP_ASYNC16(dst, src) \
    asm volatile("cp.async.cg.shared.global [%0], [%1], 16;" :: "r"(dst), "l"(src) : "memory")
#define CP_COMMIT() asm volatile("cp.async.commit_group;" ::: "memory")
#define CP_WAIT(N)  asm volatile("cp.async.wait_group %0;" :: "n"(N) : "memory")

#define LDMATRIX_X4(r0, r1, r2, r3, addr) \
    asm volatile("ldmatrix.sync.aligned.m8n8.x4.shared.b16 {%0,%1,%2,%3}, [%4];" \
        : "=r"(r0), "=r"(r1), "=r"(r2), "=r"(r3) : "r"(addr))

#define MMA_BF16(d, a, b0, b1) \
    asm volatile("mma.sync.aligned.m16n8k16.row.col.f32.bf16.bf16.f32 " \
        "{%0,%1,%2,%3}, {%4,%5,%6,%7}, {%8,%9}, {%0,%1,%2,%3};" \
        : "+f"((d)[0]), "+f"((d)[1]), "+f"((d)[2]), "+f"((d)[3]) \
        : "r"((a)[0]), "r"((a)[1]), "r"((a)[2]), "r"((a)[3]), "r"(b0), "r"(b1))

// ---------------------------------------------------------------------------
// split conversion: fp32 [M,K] -> bf16 [M,3K]
// bmode=0: [hi | hi | lo]    bmode=1: [hi | lo | hi]
// ---------------------------------------------------------------------------
__global__ void split_kernel(const float* __restrict__ in, __nv_bfloat16* __restrict__ out,
                             int K, int bmode, size_t total)
{
    for (size_t e = (size_t)blockIdx.x * blockDim.x + threadIdx.x; e < total;
         e += (size_t)gridDim.x * blockDim.x) {
        size_t m = e / (size_t)K;
        int k = (int)(e - m * (size_t)K);
        float v = in[e];
        __nv_bfloat16 hi = __float2bfloat16(v);
        __nv_bfloat16 lo = __float2bfloat16(v - __bfloat162float(hi));
        __nv_bfloat16* row = out + m * (size_t)(3 * K);
        row[k]         = hi;
        row[K + k]     = bmode ? lo : hi;
        row[2 * K + k] = bmode ? hi : lo;
    }
}

// ---------------------------------------------------------------------------
// HMMA bf16 NT GEMM.  Tile 128x128, BK=64, 256 thr (8 warps 4m x 2n),
// 3-stage cp.async, padded stride 144B.
// ---------------------------------------------------------------------------
#define GBK        64
#define G_STRIDE_B 144
#define G_TILE_B   (128 * G_STRIDE_B)          // 18432
#define G_NSTAGE   3
#define GEMM_SMEM  (G_NSTAGE * 2 * G_TILE_B)   // 110592

__global__ __launch_bounds__(256, 2)
void gemm_bf16_nt(const __nv_bfloat16* __restrict__ A, const __nv_bfloat16* __restrict__ B,
                  float* __restrict__ C, int N, int Kp)
{
    extern __shared__ char smraw[];
    const uint32_t smem = smem_u32(smraw);

    const int tid    = threadIdx.x;
    const int lane   = tid & 31;
    const int wid    = tid >> 5;
    const int warp_m = wid & 3;
    const int warp_n = wid >> 2;

    const __nv_bfloat16* Ag = A + (size_t)blockIdx.y * 128 * Kp;
    const __nv_bfloat16* Bg = B + (size_t)blockIdx.x * 128 * Kp;
    const int nch = Kp / GBK;

    auto load_chunk = [&](int chunk, int buf) {
        const uint32_t sa = smem + buf * 2 * G_TILE_B;
        const uint32_t sb = sa + G_TILE_B;
        const int k0 = chunk * GBK;
#pragma unroll
        for (int j = 0; j < 4; j++) {
            const int p   = tid + (j << 8);
            const int row = p >> 3;
            const int c16 = p & 7;
            const uint32_t off = (uint32_t)(row * G_STRIDE_B + c16 * 16);
            const size_t gsrc = (size_t)row * Kp + k0 + c16 * 8;
            CP_ASYNC16(sa + off, Ag + gsrc);
            CP_ASYNC16(sb + off, Bg + gsrc);
        }
        CP_COMMIT();
    };

    float acc[2][8][4];
#pragma unroll
    for (int t = 0; t < 2; t++)
#pragma unroll
        for (int n = 0; n < 8; n++)
#pragma unroll
            for (int x = 0; x < 4; x++) acc[t][n][x] = 0.f;

    load_chunk(0, 0);
    load_chunk(1, 1);

    const uint32_t lm_row = (uint32_t)((lane & 15) * G_STRIDE_B + (lane >> 4) * 16);
    const uint32_t a_off  = (uint32_t)(warp_m * 32 * G_STRIDE_B) + lm_row;
    const uint32_t b_off  = (uint32_t)(warp_n * 64 * G_STRIDE_B) + lm_row;

    for (int i = 0; i < nch; i++) {
        if (i == nch - 1) { CP_WAIT(0); } else { CP_WAIT(1); }
        __syncthreads();
        if (i + 2 < nch) load_chunk(i + 2, (i + 2) % G_NSTAGE);

        const uint32_t sa = smem + (i % G_NSTAGE) * 2 * G_TILE_B;
        const uint32_t sb = sa + G_TILE_B;
#pragma unroll
        for (int s = 0; s < 4; s++) {
            const uint32_t ks = (uint32_t)(s * 32);
            uint32_t af[2][4];
#pragma unroll
            for (int t = 0; t < 2; t++)
                LDMATRIX_X4(af[t][0], af[t][1], af[t][2], af[t][3],
                            sa + a_off + (uint32_t)(t * 16 * G_STRIDE_B) + ks);
            uint32_t bfr[4][4];
#pragma unroll
            for (int p = 0; p < 4; p++)
                LDMATRIX_X4(bfr[p][0], bfr[p][1], bfr[p][2], bfr[p][3],
                            sb + b_off + (uint32_t)(p * 16 * G_STRIDE_B) + ks);
#pragma unroll
            for (int t = 0; t < 2; t++)
#pragma unroll
                for (int p = 0; p < 4; p++) {
                    MMA_BF16(acc[t][2 * p],     af[t], bfr[p][0], bfr[p][2]);
                    MMA_BF16(acc[t][2 * p + 1], af[t], bfr[p][1], bfr[p][3]);
                }
        }
    }

#pragma unroll
    for (int t = 0; t < 2; t++) {
        const int row0 = blockIdx.y * 128 + warp_m * 32 + t * 16 + (lane >> 2);
#pragma unroll
        for (int n = 0; n < 8; n++) {
            const int col = blockIdx.x * 128 + warp_n * 64 + n * 8 + (lane & 3) * 2;
            *(float2*)(C + (size_t)row0 * N + col) =
                make_float2(acc[t][n][0], acc[t][n][1]);
            *(float2*)(C + (size_t)(row0 + 8) * N + col) =
                make_float2(acc[t][n][2], acc[t][n][3]);
        }
    }
}

// ---------------------------------------------------------------------------
// RoPE + hi/lo split from fused g_QKV:  Q' = [Qh|Ql] (scaled), K' = [Kh|Kl].
// ---------------------------------------------------------------------------
__global__ void rope_split_kernel()
{
    const int t = blockIdx.x;
    const int b = blockIdx.y;
    const float LOG2_10000_OVER_64 = 0.20762050593045952f;
    const float* base = g_QKV + (size_t)(b * T_ + t) * NQKV;

    for (int idx = threadIdx.x; idx < NH * 64; idx += blockDim.x) {
        const int head = idx >> 6;
        const int i    = idx & 63;
        const float invf = exp2f(-(float)i * LOG2_10000_OVER_64);
        float s, c;
        sincosf((float)t * invf, &s, &c);
        const float* p = base + head * HD;
        float q1 = p[i], q2 = p[i + 64];
        float r1 = (q1 * c - q2 * s) * SCALE_LOG2E;
        float r2 = (q1 * s + q2 * c) * SCALE_LOG2E;
        __nv_bfloat16 h1 = __float2bfloat16(r1);
        __nv_bfloat16 h2 = __float2bfloat16(r2);
        __nv_bfloat16* row = g_Qe + ((size_t)(b * NH + head) * T_ + t) * 256;
        row[i]       = h1;  row[i + 64]  = h2;
        row[128 + i] = __float2bfloat16(r1 - __bfloat162float(h1));
        row[192 + i] = __float2bfloat16(r2 - __bfloat162float(h2));
    }
    for (int idx = threadIdx.x; idx < NKV * 64; idx += blockDim.x) {
        const int kvh = idx >> 6;
        const int i   = idx & 63;
        const float invf = exp2f(-(float)i * LOG2_10000_OVER_64);
        float s, c;
        sincosf((float)t * invf, &s, &c);
        const float* p = base + D_ + kvh * HD;
        float q1 = p[i], q2 = p[i + 64];
        float r1 = q1 * c - q2 * s;
        float r2 = q1 * s + q2 * c;
        __nv_bfloat16 h1 = __float2bfloat16(r1);
        __nv_bfloat16 h2 = __float2bfloat16(r2);
        __nv_bfloat16* row = g_Ke + ((size_t)(b * NKV + kvh) * T_ + t) * 256;
        row[i]       = h1;  row[i + 64]  = h2;
        row[128 + i] = __float2bfloat16(r1 - __bfloat162float(h1));
        row[192 + i] = __float2bfloat16(r2 - __bfloat162float(h2));
    }
}

// V transpose + split (coalesced, smem tile):
// g_QKV[.., 2560 + kvh*HD + d] -> g_Vth/g_Vtl [b,kvh,d,t]
__global__ void v_split_kernel()   // grid (T_/32, B_*NKV), 256 thr
{
    __shared__ float ts[32][129];
    const int t0 = blockIdx.x * 32;
    const int bz = blockIdx.y;
    const int b = bz >> 2, kvh = bz & 3;
    const float* src = g_QKV + (size_t)(b * T_ + t0) * NQKV + D_ + KVD + kvh * HD;
#pragma unroll
    for (int k = 0; k < 16; k++) {
        const int idx = threadIdx.x + k * 256;
        const int d = idx & 127, t = idx >> 7;
        ts[t][d] = src[(size_t)t * NQKV + d];
    }
    __syncthreads();
    __nv_bfloat16* dh = g_Vth + (size_t)bz * HD * T_ + t0;
    __nv_bfloat16* dl = g_Vtl + (size_t)bz * HD * T_ + t0;
#pragma unroll
    for (int k = 0; k < 16; k++) {
        const int idx = threadIdx.x + k * 256;
        const int t = idx & 31, d = idx >> 5;
        const float v = ts[t][d];
        __nv_bfloat16 hi = __float2bfloat16(v);
        dh[(size_t)d * T_ + t] = hi;
        dl[(size_t)d * T_ + t] = __float2bfloat16(v - __bfloat162float(hi));
    }
}

// ---------------------------------------------------------------------------
// HMMA flash attention.  CTA = (b, h, 128 Q rows), 256 thr, warp = 16 rows x
// 128 cols.  4 x 64-col chunks per phase; symmetric software pipeline:
// V(j) prefetched during QK MMAs, K(j+1) prefetched during PV MMAs.
// Epilogue writes hi/hi/lo bf16 straight into g_AE.
// ---------------------------------------------------------------------------
#define AT_QROWB 528                       // 256 bf16 + 16B pad
#define AT_PROWB 272                       // 128 bf16 + 16B pad
#define AT_CH_B  18432                     // 128 rows x 144B
#define SQ_OFF   0
#define SPH_OFF  (128 * AT_QROWB)                  // 67584
#define SPL_OFF  (SPH_OFF + 128 * AT_PROWB)        // 102400
#define SKV_OFF  (SPL_OFF + 128 * AT_PROWB)        // 137216
#define ATT_SMEM (SKV_OFF + 4 * AT_CH_B)           // 210944

__global__ __launch_bounds__(256, 1) void attn_mma()
{
    extern __shared__ char smraw[];
    const uint32_t sb0 = smem_u32(smraw);

    const int tid  = threadIdx.x;
    const int lane = tid & 31;
    const int w    = tid >> 5;
    const int qi   = 15 - (int)blockIdx.x;    // big tiles first
    const int h    = blockIdx.y;
    const int b    = blockIdx.z;
    const int kvh  = h >> 2;

    const __nv_bfloat16* Qg  = g_Qe + ((size_t)(b * NH + h) * T_ + qi * 128) * 256;
    const __nv_bfloat16* Kg  = g_Ke + ((size_t)(b * NKV + kvh) * T_) * 256;
    const __nv_bfloat16* Vhg = g_Vth + (size_t)(b * NKV + kvh) * HD * T_;
    const __nv_bfloat16* Vlg = g_Vtl + (size_t)(b * NKV + kvh) * HD * T_;

    // resident Q' tile (128 x 256 bf16)
    {
        const int row = tid >> 1, half = tid & 1;
#pragma unroll
        for (int jj = 0; jj < 16; jj++) {
            const int c16 = half * 16 + jj;
            CP_ASYNC16(sb0 + SQ_OFF + (uint32_t)(row * AT_QROWB + c16 * 16),
                       Qg + (size_t)row * 256 + c16 * 8);
        }
        CP_COMMIT();
    }

    // K chunk c (64 head-dims): c0,c1 = Kh halves, c2,c3 = Kl halves
    auto load_k = [&](int j, int c, int st) {
#pragma unroll
        for (int jj = 0; jj < 4; jj++) {
            const int p   = tid + (jj << 8);
            const int row = p >> 3;
            const int c16 = p & 7;
            CP_ASYNC16(sb0 + SKV_OFF + st * AT_CH_B + (uint32_t)(row * 144 + c16 * 16),
                       Kg + (size_t)(j * 128 + row) * 256 + c * 64 + c16 * 8);
        }
        CP_COMMIT();
    };
    // V chunk c (64 t-cols): c0,c1 = Vh halves, c2,c3 = Vl halves
    auto load_v = [&](int j, int c, int st) {
        const __nv_bfloat16* Vg = (c < 2) ? Vhg : Vlg;
        const int toff = j * 128 + (c & 1) * 64;
#pragma unroll
        for (int jj = 0; jj < 4; jj++) {
            const int p   = tid + (jj << 8);
            const int row = p >> 3;
            const int c16 = p & 7;
            CP_ASYNC16(sb0 + SKV_OFF + st * AT_CH_B + (uint32_t)(row * 144 + c16 * 16),
                       Vg + (size_t)row * T_ + toff + c16 * 8);
        }
        CP_COMMIT();
    };

    float o[16][4];
#pragma unroll
    for (int n = 0; n < 16; n++)
#pragma unroll
        for (int x = 0; x < 4; x++) o[n][x] = 0.f;
    float m0 = -1e30f, m1 = -1e30f, l0 = 0.f, l1 = 0.f;

    const uint32_t lm144   = (uint32_t)((lane & 15) * 144 + (lane >> 4) * 16);
    const uint32_t aq_base = sb0 + SQ_OFF + (uint32_t)((w * 16 + (lane & 15)) * AT_QROWB + (lane >> 4) * 16);
    const uint32_t ap_row  = (uint32_t)((w * 16 + (lane & 15)) * AT_PROWB + (lane >> 4) * 16);
    const int rloc0 = w * 16 + (lane >> 2);
    const int cbase = (lane & 3) * 2;

    // preamble K chunks for j=0
    load_k(0, 0, 0); load_k(0, 1, 1); load_k(0, 2, 2); load_k(0, 3, 3);

    for (int j = 0; j <= qi; j++) {
        float s[16][4];
#pragma unroll
        for (int n = 0; n < 16; n++)
#pragma unroll
            for (int x = 0; x < 4; x++) s[n][x] = 0.f;

        // ================= QK phase (V(j) prefetch interleaved) ===========
#pragma unroll
        for (int c = 0; c < 4; c++) {
            if (c == 0) { CP_WAIT(3); } else { CP_WAIT(2); }
            __syncthreads();
            if (c >= 1) load_v(j, c - 1, c - 1);

            const uint32_t sbK = sb0 + SKV_OFF + c * AT_CH_B;
            const uint32_t qsl = (uint32_t)((c & 1) * 128);
#pragma unroll
            for (int ks = 0; ks < 4; ks++) {
                const uint32_t ko = (uint32_t)(ks * 32);
                uint32_t bfr[8][4];
#pragma unroll
                for (int p = 0; p < 8; p++)
                    LDMATRIX_X4(bfr[p][0], bfr[p][1], bfr[p][2], bfr[p][3],
                                sbK + (uint32_t)(p * 16 * 144) + lm144 + ko);
                uint32_t af[4];
                LDMATRIX_X4(af[0], af[1], af[2], af[3], aq_base + qsl + ko);
#pragma unroll
                for (int p = 0; p < 8; p++) {
                    MMA_BF16(s[2 * p],     af, bfr[p][0], bfr[p][2]);
                    MMA_BF16(s[2 * p + 1], af, bfr[p][1], bfr[p][3]);
                }
                if (c < 2) {   // Kh also pairs with Ql (at +256B)
                    uint32_t ag[4];
                    LDMATRIX_X4(ag[0], ag[1], ag[2], ag[3], aq_base + qsl + 256u + ko);
#pragma unroll
                    for (int p = 0; p < 8; p++) {
                        MMA_BF16(s[2 * p],     ag, bfr[p][0], bfr[p][2]);
                        MMA_BF16(s[2 * p + 1], ag, bfr[p][1], bfr[p][3]);
                    }
                }
            }
        }
        __syncthreads();           // buf3 K consumed by all warps
        load_v(j, 3, 3);

        // ---- causal mask (diagonal block) ----
        if (j == qi) {
#pragma unroll
            for (int n = 0; n < 16; n++) {
                const int col = n * 8 + cbase;
#pragma unroll
                for (int x = 0; x < 4; x++) {
                    const int cc = col + (x & 1);
                    const int rr = rloc0 + ((x >> 1) << 3);
                    if (cc > rr) s[n][x] = -1e30f;
                }
            }
        }

        // ---- online softmax (quad-local rows) ----
        float mx0 = -1e30f, mx1 = -1e30f;
#pragma unroll
        for (int n = 0; n < 16; n++) {
            mx0 = fmaxf(mx0, fmaxf(s[n][0], s[n][1]));
            mx1 = fmaxf(mx1, fmaxf(s[n][2], s[n][3]));
        }
        mx0 = fmaxf(mx0, __shfl_xor_sync(0xffffffffu, mx0, 1));
        mx0 = fmaxf(mx0, __shfl_xor_sync(0xffffffffu, mx0, 2));
        mx1 = fmaxf(mx1, __shfl_xor_sync(0xffffffffu, mx1, 1));
        mx1 = fmaxf(mx1, __shfl_xor_sync(0xffffffffu, mx1, 2));

        const float mn0 = fmaxf(m0, mx0), mn1 = fmaxf(m1, mx1);
        const float a0 = exp2f(m0 - mn0), a1 = exp2f(m1 - mn1);
        m0 = mn0; m1 = mn1;

        float sum0 = 0.f, sum1 = 0.f;
        char* smc = smraw;
#pragma unroll
        for (int n = 0; n < 16; n++) {
            const float p0 = exp2f(s[n][0] - mn0);
            const float p1 = exp2f(s[n][1] - mn0);
            const float p2 = exp2f(s[n][2] - mn1);
            const float p3 = exp2f(s[n][3] - mn1);
            sum0 += p0 + p1;
            sum1 += p2 + p3;
            const __nv_bfloat16 h0 = __float2bfloat16(p0), h1b = __float2bfloat16(p1);
            const __nv_bfloat16 h2 = __float2bfloat16(p2), h3b = __float2bfloat16(p3);
            const int colb = (n * 8 + cbase) * 2;
            const int ra = w * 16 + (lane >> 2);
            *(__nv_bfloat162*)(smc + SPH_OFF + ra * AT_PROWB + colb) =
                __nv_bfloat162(h0, h1b);
            *(__nv_bfloat162*)(smc + SPH_OFF + (ra + 8) * AT_PROWB + colb) =
                __nv_bfloat162(h2, h3b);
            *(__nv_bfloat162*)(smc + SPL_OFF + ra * AT_PROWB + colb) =
                __nv_bfloat162(__float2bfloat16(p0 - __bfloat162float(h0)),
                               __float2bfloat16(p1 - __bfloat162float(h1b)));
            *(__nv_bfloat162*)(smc + SPL_OFF + (ra + 8) * AT_PROWB + colb) =
                __nv_bfloat162(__float2bfloat16(p2 - __bfloat162float(h2)),
                               __float2bfloat16(p3 - __bfloat162float(h3b)));
        }
        sum0 += __shfl_xor_sync(0xffffffffu, sum0, 1);
        sum0 += __shfl_xor_sync(0xffffffffu, sum0, 2);
        sum1 += __shfl_xor_sync(0xffffffffu, sum1, 1);
        sum1 += __shfl_xor_sync(0xffffffffu, sum1, 2);
        l0 = l0 * a0 + sum0;
        l1 = l1 * a1 + sum1;

#pragma unroll
        for (int n = 0; n < 16; n++) {
            o[n][0] *= a0; o[n][1] *= a0; o[n][2] *= a1; o[n][3] *= a1;
        }

        // ================= PV phase (K(j+1) prefetch interleaved) =========
        const bool more = (j < qi);
#pragma unroll
        for (int c = 0; c < 4; c++) {
            if (c == 0) { CP_WAIT(3); } else { CP_WAIT(2); }
            __syncthreads();
            if (c >= 1) { if (more) load_k(j + 1, c - 1, c - 1); else CP_COMMIT(); }

            const uint32_t sbV = sb0 + SKV_OFF + c * AT_CH_B;
            const uint32_t psl = (uint32_t)((c & 1) * 128);
#pragma unroll
            for (int ks = 0; ks < 4; ks++) {
                const uint32_t ko = (uint32_t)(ks * 32);
                uint32_t bfr[8][4];
#pragma unroll
                for (int p = 0; p < 8; p++)
                    LDMATRIX_X4(bfr[p][0], bfr[p][1], bfr[p][2], bfr[p][3],
                                sbV + (uint32_t)(p * 16 * 144) + lm144 + ko);
                uint32_t af[4];
                LDMATRIX_X4(af[0], af[1], af[2], af[3],
                            sb0 + SPH_OFF + ap_row + psl + ko);
#pragma unroll
                for (int p = 0; p < 8; p++) {
                    MMA_BF16(o[2 * p],     af, bfr[p][0], bfr[p][2]);
                    MMA_BF16(o[2 * p + 1], af, bfr[p][1], bfr[p][3]);
                }
                if (c < 2) {   // Vh also pairs with Pl
                    uint32_t ag[4];
                    LDMATRIX_X4(ag[0], ag[1], ag[2], ag[3],
                                sb0 + SPL_OFF + ap_row + psl + ko);
#pragma unroll
                    for (int p = 0; p < 8; p++) {
                        MMA_BF16(o[2 * p],     ag, bfr[p][0], bfr[p][2]);
                        MMA_BF16(o[2 * p + 1], ag, bfr[p][1], bfr[p][3]);
                    }
                }
            }
        }
        __syncthreads();           // buf3 V consumed
        if (more) load_k(j + 1, 3, 3); else CP_COMMIT();
    }

    // ---- epilogue: normalize + hi/hi/lo split straight into g_AE ----
    const float il0 = 1.f / l0, il1 = 1.f / l1;
    const int grow0 = qi * 128 + rloc0;
    __nv_bfloat16* r0 = g_AE + (size_t)(b * T_ + grow0) * KP;
    __nv_bfloat16* r1 = g_AE + (size_t)(b * T_ + grow0 + 8) * KP;
#pragma unroll
    for (int n = 0; n < 16; n++) {
        const int col = h * HD + n * 8 + cbase;
        float v0 = o[n][0] * il0, v1 = o[n][1] * il0;
        float v2 = o[n][2] * il1, v3 = o[n][3] * il1;
        __nv_bfloat16 a = __float2bfloat16(v0), bb = __float2bfloat16(v1);
        __nv_bfloat16 cc = __float2bfloat16(v2), dd = __float2bfloat16(v3);
        *(__nv_bfloat162*)(r0 + col)          = __nv_bfloat162(a, bb);
        *(__nv_bfloat162*)(r0 + D_ + col)     = __nv_bfloat162(a, bb);
        *(__nv_bfloat162*)(r0 + 2 * D_ + col) =
            __nv_bfloat162(__float2bfloat16(v0 - __bfloat162float(a)),
                           __float2bfloat16(v1 - __bfloat162float(bb)));
        *(__nv_bfloat162*)(r1 + col)          = __nv_bfloat162(cc, dd);
        *(__nv_bfloat162*)(r1 + D_ + col)     = __nv_bfloat162(cc, dd);
        *(__nv_bfloat162*)(r1 + 2 * D_ + col) =
            __nv_bfloat162(__float2bfloat16(v2 - __bfloat162float(cc)),
                           __float2bfloat16(v3 - __bfloat162float(dd)));
    }
}

// ---------------------------------------------------------------------------
extern "C" void kernel_launch(void* const* d_in, const int* in_sizes, int n_in,
                              void* d_out, int out_size)
{
    const float* x  = (const float*)d_in[0];
    const float* Wq = (const float*)d_in[1];
    const float* Wk = (const float*)d_in[2];
    const float* Wv = (const float*)d_in[3];
    const float* Wo = (const float*)d_in[4];
    float* out = (float*)d_out;

    float* QKVb;
    __nv_bfloat16 *AE, *WQKVE, *WOE;
    cudaGetSymbolAddress((void**)&QKVb, g_QKV);
    cudaGetSymbolAddress((void**)&AE, g_AE);
    cudaGetSymbolAddress((void**)&WQKVE, g_WQKVE);
    cudaGetSymbolAddress((void**)&WOE, g_WOE);

    const int M = B_ * T_;  // 8192

    cudaFuncSetAttribute(gemm_bf16_nt, cudaFuncAttributeMaxDynamicSharedMemorySize,
                         GEMM_SMEM);
    cudaFuncSetAttribute(attn_mma, cudaFuncAttributeMaxDynamicSharedMemorySize,
                         ATT_SMEM);

    // split conversions (Wq|Wk|Wv stacked into one weight buffer)
    split_kernel<<<4096, 256>>>(x,  AE, D_, 0, (size_t)M * D_);
    split_kernel<<<2048, 256>>>(Wq, WQKVE,                        D_, 1, (size_t)D_ * D_);
    split_kernel<<<1024, 256>>>(Wk, WQKVE + (size_t)D_ * KP,      D_, 1, (size_t)KVD * D_);
    split_kernel<<<1024, 256>>>(Wv, WQKVE + (size_t)(D_+KVD) * KP, D_, 1, (size_t)KVD * D_);
    split_kernel<<<2048, 256>>>(Wo, WOE, D_, 1, (size_t)D_ * D_);

    // fused QKV projection (one GEMM, N=3072)
    gemm_bf16_nt<<<dim3(NQKV / 128, M / 128), 256, GEMM_SMEM>>>(AE, WQKVE, QKVb, NQKV, KP);

    // attention operand prep
    rope_split_kernel<<<dim3(T_, B_), 256>>>();
    v_split_kernel<<<dim3(T_ / 32, B_ * NKV), 256>>>();

    // tensor-core flash attention (writes split output into AE)
    attn_mma<<<dim3(T_ / 128, NH, B_), 256, ATT_SMEM>>>();

    // output projection
    gemm_bf16_nt<<<dim3(D_ / 128, M / 128), 256, GEMM_SMEM>>>(AE, WOE, out, D_, KP);
}